// round 2
// baseline (speedup 1.0000x reference)
#include <cuda_runtime.h>
#include <math.h>

// ---------------------------------------------------------------------------
// Problem dims
// ---------------------------------------------------------------------------
#define NB      8
#define LQ      512
#define LKV     16384
#define CH_LAT  1024
#define CH_IN   768
#define DH      128
#define NH      8
#define BH      (NB*NH)        // 64
#define MKV     (NB*LKV)       // 131072
#define MQ      (NB*LQ)        // 4096

// ---------------------------------------------------------------------------
// Scratch (device globals -- no allocations allowed)
// ---------------------------------------------------------------------------
__device__ float g_mu_kv[MKV];
__device__ float g_rs_kv[MKV];
__device__ float g_mu_q[MQ];
__device__ float g_rs_q[MQ];
__device__ float g_Qb[(size_t)BH*LQ*DH];     //  16 MB  [bh][q][d], pre-scaled by 1/sqrt(d)
__device__ float g_Kb[(size_t)BH*LKV*DH];    // 536 MB  [bh][l][d]
__device__ float g_Vb[(size_t)BH*LKV*DH];    // 536 MB  [bh][l][d]
__device__ float g_AO[(size_t)MQ*1024];      //  16 MB  [b*512+q][h*128+d]

// ---------------------------------------------------------------------------
// Row stats for LayerNorm (one warp per row)
// ---------------------------------------------------------------------------
__global__ void rowstats_kernel(const float* __restrict__ X, float* __restrict__ mu,
                                float* __restrict__ rs, int cols)
{
    int row  = blockIdx.x * 8 + (threadIdx.x >> 5);
    int lane = threadIdx.x & 31;
    const float* xr = X + (size_t)row * cols;
    float s = 0.f, s2 = 0.f;
    for (int c = lane; c < cols; c += 32) { float v = xr[c]; s += v; s2 += v * v; }
#pragma unroll
    for (int o = 16; o; o >>= 1) {
        s  += __shfl_xor_sync(0xffffffffu, s,  o);
        s2 += __shfl_xor_sync(0xffffffffu, s2, o);
    }
    if (lane == 0) {
        float m   = s / cols;
        float var = fmaxf(s2 / cols - m * m, 0.f);
        mu[row] = m;
        rs[row] = rsqrtf(var + 1e-5f);
    }
}

// ---------------------------------------------------------------------------
// 128x128x16 SGEMM, 256 threads, 8x8 per thread.
// MODE 0: A=input_kv (LN fused), B = [W_K | W_V] (N=2048), scatter into g_Kb/g_Vb
// MODE 1: A=latent   (LN fused), B = W_Q, scale folded, scatter into g_Qb
// MODE 2: A=g_AO, B = W_O, plain row-major store to d_out
// All weight matrices have leading dim 1024.
// ---------------------------------------------------------------------------
template<int MODE>
__global__ __launch_bounds__(256)
void gemm128(const float* __restrict__ A,
             const float* __restrict__ W0, const float* __restrict__ W1,
             const float* __restrict__ mu, const float* __restrict__ rs,
             const float* __restrict__ gamma, const float* __restrict__ beta,
             float* __restrict__ C0, float* __restrict__ C1,
             int K)
{
    const int BK = 16;
    __shared__ float As[BK][128];
    __shared__ float Bs[BK][128];

    const int tid = threadIdx.x;
    const int tx = tid & 15, ty = tid >> 4;
    const int m0 = blockIdx.y * 128;
    const int n0 = blockIdx.x * 128;

    const float* Wp = W0;
    int wcol0 = n0;
    if (MODE == 0 && n0 >= 1024) { Wp = W1; wcol0 = n0 - 1024; }

    const int a_row = tid >> 1;            // 0..127
    const int a_k   = (tid & 1) << 3;      // 0 or 8
    const int b_row = tid >> 4;            // 0..15
    const int b_col = (tid & 15) << 3;     // 0..120

    float a_mu = 0.f, a_rs = 0.f;
    if (MODE != 2) { a_mu = mu[m0 + a_row]; a_rs = rs[m0 + a_row]; }
    const float* Arow = A + (size_t)(m0 + a_row) * K;

    float acc[8][8];
#pragma unroll
    for (int i = 0; i < 8; i++)
#pragma unroll
        for (int j = 0; j < 8; j++) acc[i][j] = 0.f;

    for (int k0 = 0; k0 < K; k0 += BK) {
        // ---- A tile (LN fused for modes 0/1), stored transposed As[k][m]
#pragma unroll
        for (int half = 0; half < 2; half++) {
            float4 v = *(const float4*)(Arow + k0 + a_k + half * 4);
            float vv[4] = {v.x, v.y, v.z, v.w};
#pragma unroll
            for (int u = 0; u < 4; u++) {
                int kk = a_k + half * 4 + u;
                float val = vv[u];
                if (MODE != 2)
                    val = (val - a_mu) * a_rs * __ldg(&gamma[k0 + kk]) + __ldg(&beta[k0 + kk]);
                As[kk][a_row] = val;
            }
        }
        // ---- B tile
        {
            const float* Brow = Wp + (size_t)(k0 + b_row) * 1024 + wcol0 + b_col;
            float4 w0 = *(const float4*)(Brow);
            float4 w1 = *(const float4*)(Brow + 4);
            *(float4*)&Bs[b_row][b_col]     = w0;
            *(float4*)&Bs[b_row][b_col + 4] = w1;
        }
        __syncthreads();
#pragma unroll 4
        for (int kk = 0; kk < BK; kk++) {
            float a[8], b[8];
            *(float4*)&a[0] = *(const float4*)&As[kk][ty * 8];
            *(float4*)&a[4] = *(const float4*)&As[kk][ty * 8 + 4];
            *(float4*)&b[0] = *(const float4*)&Bs[kk][tx * 8];
            *(float4*)&b[4] = *(const float4*)&Bs[kk][tx * 8 + 4];
#pragma unroll
            for (int i = 0; i < 8; i++)
#pragma unroll
                for (int j = 0; j < 8; j++)
                    acc[i][j] += a[i] * b[j];
        }
        __syncthreads();
    }

    // ---- store
#pragma unroll
    for (int i = 0; i < 8; i++) {
        int r = m0 + ty * 8 + i;
#pragma unroll
        for (int j = 0; j < 8; j++) {
            int c = n0 + tx * 8 + j;
            float v = acc[i][j];
            if (MODE == 0) {
                int part = c >> 10;
                int cc = c & 1023;
                int h = cc >> 7, d = cc & 127;
                int bb = r >> 14, l = r & 16383;
                float* dst = part ? C1 : C0;
                dst[(((size_t)(bb * 8 + h) << 14) + l) * 128 + d] = v;
            } else if (MODE == 1) {
                int h = c >> 7, d = c & 127;
                int bb = r >> 9, q = r & 511;
                C0[(((size_t)(bb * 8 + h)) * 512 + q) * 128 + d] = 0.08838834764831845f * v;
            } else {
                C0[(size_t)r * 1024 + c] = v;
            }
        }
    }
}

// ---------------------------------------------------------------------------
// Flash attention, fp32. Br=128, Bc=64, d=128, 256 threads.
// Thread grid 16x16: S tile = rows ty*8..+8, cols {tx, tx+16, tx+32, tx+48};
//                    O tile = rows ty*8..+8, cols tx*8..+8.
// Smem: Qs[128][132], KP (Ks[64][132] reused as Ps[128][68]), Vs[64][128].
// ---------------------------------------------------------------------------
#define ATTN_SMEM_FLOATS (128*132 + 8704 + 64*128)
#define ATTN_SMEM_BYTES  (ATTN_SMEM_FLOATS * 4)

__global__ __launch_bounds__(256, 1)
void attn_kernel(const float* __restrict__ Qb, const float* __restrict__ Kb,
                 const float* __restrict__ Vb, float* __restrict__ AO)
{
    extern __shared__ float sm[];
    float* Qs = sm;                 // [m][132]
    float* KP = sm + 128 * 132;     // Ks [n][132]  /  Ps [m][68]
    float* Vs = KP + 8704;          // [n][128]

    const int tid = threadIdx.x;
    const int tx = tid & 15, ty = tid >> 4;
    const int bh = blockIdx.y;
    const int q0 = blockIdx.x * 128;

    const float* Qg = Qb + ((size_t)bh * LQ + q0) * DH;
    const float* Kg = Kb + (size_t)bh * LKV * DH;
    const float* Vg = Vb + (size_t)bh * LKV * DH;

    // load Q tile (coalesced read, padded-row smem write)
#pragma unroll
    for (int it = 0; it < 64; it++) {
        int idx = tid + it * 256;
        int m = idx >> 7, d = idx & 127;
        Qs[m * 132 + d] = Qg[idx];
    }

    float accO[8][8];
    float rowm[8], rowl[8];
#pragma unroll
    for (int i = 0; i < 8; i++) {
        rowm[i] = -1e30f; rowl[i] = 0.f;
#pragma unroll
        for (int j = 0; j < 8; j++) accO[i][j] = 0.f;
    }

    for (int c0 = 0; c0 < LKV; c0 += 64) {
        __syncthreads();   // prev-iter Ps/Vs readers done (and Qs visible on iter 0)
        // load K chunk (transpose-free, padded rows) and V chunk
#pragma unroll
        for (int it = 0; it < 32; it++) {
            int idx = tid + it * 256;
            int n = idx >> 7, d = idx & 127;
            KP[n * 132 + d] = Kg[(size_t)c0 * 128 + idx];
            Vs[idx]         = Vg[(size_t)c0 * 128 + idx];
        }
        __syncthreads();

        // ---- S = Q K^T (pre-scaled Q)
        float s[8][4];
#pragma unroll
        for (int i = 0; i < 8; i++)
#pragma unroll
            for (int j = 0; j < 4; j++) s[i][j] = 0.f;

#pragma unroll 2
        for (int kk = 0; kk < 128; kk += 4) {
            float4 a[8], b[4];
#pragma unroll
            for (int i = 0; i < 8; i++)
                a[i] = *(const float4*)&Qs[(ty * 8 + i) * 132 + kk];
#pragma unroll
            for (int j = 0; j < 4; j++)
                b[j] = *(const float4*)&KP[(tx + j * 16) * 132 + kk];
#pragma unroll
            for (int i = 0; i < 8; i++)
#pragma unroll
                for (int j = 0; j < 4; j++)
                    s[i][j] += a[i].x * b[j].x + a[i].y * b[j].y +
                               a[i].z * b[j].z + a[i].w * b[j].w;
        }

        // ---- online softmax (reduce across 16-lane half-warps = all 64 cols)
        float corr[8];
#pragma unroll
        for (int i = 0; i < 8; i++) {
            float rm = fmaxf(fmaxf(s[i][0], s[i][1]), fmaxf(s[i][2], s[i][3]));
#pragma unroll
            for (int o = 8; o; o >>= 1) rm = fmaxf(rm, __shfl_xor_sync(0xffffffffu, rm, o));
            float mn = fmaxf(rowm[i], rm);
            float f  = __expf(rowm[i] - mn);
            rowm[i]  = mn;
            float ls = 0.f;
#pragma unroll
            for (int j = 0; j < 4; j++) { s[i][j] = __expf(s[i][j] - mn); ls += s[i][j]; }
#pragma unroll
            for (int o = 8; o; o >>= 1) ls += __shfl_xor_sync(0xffffffffu, ls, o);
            rowl[i] = rowl[i] * f + ls;
            corr[i] = f;
        }
#pragma unroll
        for (int i = 0; i < 8; i++)
#pragma unroll
            for (int j = 0; j < 8; j++) accO[i][j] *= corr[i];

        __syncthreads();   // everyone done reading Ks before overwriting with Ps
#pragma unroll
        for (int i = 0; i < 8; i++)
#pragma unroll
            for (int j = 0; j < 4; j++)
                KP[(ty * 8 + i) * 68 + tx + j * 16] = s[i][j];
        __syncthreads();

        // ---- O += P @ V
#pragma unroll 2
        for (int kk = 0; kk < 64; kk += 4) {
            float4 a[8];
#pragma unroll
            for (int i = 0; i < 8; i++)
                a[i] = *(const float4*)&KP[(ty * 8 + i) * 68 + kk];
#pragma unroll
            for (int u = 0; u < 4; u++) {
                float4 b0 = *(const float4*)&Vs[(kk + u) * 128 + tx * 8];
                float4 b1 = *(const float4*)&Vs[(kk + u) * 128 + tx * 8 + 4];
#pragma unroll
                for (int i = 0; i < 8; i++) {
                    float av = (u == 0) ? a[i].x : (u == 1) ? a[i].y : (u == 2) ? a[i].z : a[i].w;
                    accO[i][0] += av * b0.x;  accO[i][1] += av * b0.y;
                    accO[i][2] += av * b0.z;  accO[i][3] += av * b0.w;
                    accO[i][4] += av * b1.x;  accO[i][5] += av * b1.y;
                    accO[i][6] += av * b1.z;  accO[i][7] += av * b1.w;
                }
            }
        }
    }

    // ---- epilogue: normalize and scatter to [b*512+q][h*128+d]
    int bb = bh >> 3, h = bh & 7;
#pragma unroll
    for (int i = 0; i < 8; i++) {
        float inv = 1.f / rowl[i];
        size_t rowoff = ((size_t)(bb * 512 + q0 + ty * 8 + i)) * 1024 + h * 128 + tx * 8;
#pragma unroll
        for (int j = 0; j < 8; j++)
            AO[rowoff + j] = accO[i][j] * inv;
    }
}

// ---------------------------------------------------------------------------
// Launcher (graph-capturable: kernel launches only)
// ---------------------------------------------------------------------------
extern "C" void kernel_launch(void* const* d_in, const int* in_sizes, int n_in,
                              void* d_out, int out_size)
{
    (void)in_sizes; (void)n_in; (void)out_size;
    const float* latent   = (const float*)d_in[0];
    const float* inpkv    = (const float*)d_in[1];
    const float* W_Q      = (const float*)d_in[2];
    const float* W_K      = (const float*)d_in[3];
    const float* W_V      = (const float*)d_in[4];
    const float* W_O      = (const float*)d_in[5];
    const float* ln_lat_g = (const float*)d_in[6];
    const float* ln_lat_b = (const float*)d_in[7];
    const float* ln_in_g  = (const float*)d_in[8];
    const float* ln_in_b  = (const float*)d_in[9];
    float* out = (float*)d_out;

    float *p_mukv, *p_rskv, *p_muq, *p_rsq, *p_Q, *p_K, *p_V, *p_AO;
    cudaGetSymbolAddress((void**)&p_mukv, g_mu_kv);
    cudaGetSymbolAddress((void**)&p_rskv, g_rs_kv);
    cudaGetSymbolAddress((void**)&p_muq,  g_mu_q);
    cudaGetSymbolAddress((void**)&p_rsq,  g_rs_q);
    cudaGetSymbolAddress((void**)&p_Q,    g_Qb);
    cudaGetSymbolAddress((void**)&p_K,    g_Kb);
    cudaGetSymbolAddress((void**)&p_V,    g_Vb);
    cudaGetSymbolAddress((void**)&p_AO,   g_AO);

    cudaFuncSetAttribute(attn_kernel, cudaFuncAttributeMaxDynamicSharedMemorySize,
                         ATTN_SMEM_BYTES);

    // LN row statistics
    rowstats_kernel<<<MKV / 8, 256>>>(inpkv,  p_mukv, p_rskv, CH_IN);
    rowstats_kernel<<<MQ  / 8, 256>>>(latent, p_muq,  p_rsq,  CH_LAT);

    // Q projection (LN fused, softmax scale folded)
    gemm128<1><<<dim3(8, MQ / 128), 256>>>(latent, W_Q, nullptr,
                                           p_muq, p_rsq, ln_lat_g, ln_lat_b,
                                           p_Q, nullptr, CH_LAT);
    // K|V projection (LN fused, one pass over input_kv)
    gemm128<0><<<dim3(16, MKV / 128), 256>>>(inpkv, W_K, W_V,
                                             p_mukv, p_rskv, ln_in_g, ln_in_b,
                                             p_K, p_V, CH_IN);
    // flash attention
    attn_kernel<<<dim3(4, BH), 256, ATTN_SMEM_BYTES>>>(p_Q, p_K, p_V, p_AO);

    // output projection
    gemm128<2><<<dim3(8, MQ / 128), 256>>>(p_AO, W_O, nullptr,
                                           nullptr, nullptr, nullptr, nullptr,
                                           out, nullptr, 1024);
}

// round 3
// speedup vs baseline: 1.2256x; 1.2256x over previous
#include <cuda_runtime.h>
#include <math.h>

// ---------------------------------------------------------------------------
// Problem dims
// ---------------------------------------------------------------------------
#define NB      8
#define LQ      512
#define LKV     16384
#define CH_LAT  1024
#define CH_IN   768
#define DH      128
#define NH      8
#define BH      (NB*NH)        // 64
#define MKV     (NB*LKV)       // 131072
#define MQ      (NB*LQ)        // 4096

// ---------------------------------------------------------------------------
// Scratch (device globals -- no allocations allowed)
// ---------------------------------------------------------------------------
__device__ float g_mu_kv[MKV];
__device__ float g_rs_kv[MKV];
__device__ float g_mu_q[MQ];
__device__ float g_rs_q[MQ];
__device__ float g_Qb[(size_t)BH*LQ*DH];     //  16 MB  [bh][q][d], pre-scaled by 1/sqrt(d)
__device__ float g_Kb[(size_t)BH*LKV*DH];    // 536 MB  [bh][l][d]
__device__ float g_Vb[(size_t)BH*LKV*DH];    // 536 MB  [bh][l][d]
__device__ float g_AO[(size_t)MQ*1024];      //  16 MB  [b*512+q][h*128+d]

// ---------------------------------------------------------------------------
// tf32 helpers
// ---------------------------------------------------------------------------
__device__ __forceinline__ unsigned f2tf(float x) {
    unsigned r;
    asm("cvt.rna.tf32.f32 %0, %1;" : "=r"(r) : "f"(x));
    return r;
}

__device__ __forceinline__ void mma_tf32(float* c, const unsigned* a, const unsigned* b) {
    asm volatile(
        "mma.sync.aligned.m16n8k8.row.col.f32.tf32.tf32.f32 "
        "{%0,%1,%2,%3}, {%4,%5,%6,%7}, {%8,%9}, {%0,%1,%2,%3};\n"
        : "+f"(c[0]), "+f"(c[1]), "+f"(c[2]), "+f"(c[3])
        : "r"(a[0]), "r"(a[1]), "r"(a[2]), "r"(a[3]), "r"(b[0]), "r"(b[1]));
}

// ---------------------------------------------------------------------------
// Row stats for LayerNorm (one warp per row)
// ---------------------------------------------------------------------------
__global__ void rowstats_kernel(const float* __restrict__ X, float* __restrict__ mu,
                                float* __restrict__ rs, int cols)
{
    int row  = blockIdx.x * 8 + (threadIdx.x >> 5);
    int lane = threadIdx.x & 31;
    const float* xr = X + (size_t)row * cols;
    float s = 0.f, s2 = 0.f;
    for (int c = lane; c < cols; c += 32) { float v = xr[c]; s += v; s2 += v * v; }
#pragma unroll
    for (int o = 16; o; o >>= 1) {
        s  += __shfl_xor_sync(0xffffffffu, s,  o);
        s2 += __shfl_xor_sync(0xffffffffu, s2, o);
    }
    if (lane == 0) {
        float m   = s / cols;
        float var = fmaxf(s2 / cols - m * m, 0.f);
        mu[row] = m;
        rs[row] = rsqrtf(var + 1e-5f);
    }
}

// ---------------------------------------------------------------------------
// Tensor-core TF32 GEMM: 128x128 block, BK=32, 256 threads (8 warps 2x4),
// warp tile 64x32 = 4x4 m16n8k8. A/B staged in smem in fragment-permuted
// layout (tf32 bits). LN fused into A loads (MODE 0/1).
// MODE 0: A=input_kv, B=[W_K|W_V] (N=2048), scatter -> g_Kb/g_Vb
// MODE 1: A=latent,   B=W_Q, scale folded,   scatter -> g_Qb
// MODE 2: A=g_AO,     B=W_O, plain row-major store
// ---------------------------------------------------------------------------
template<int MODE>
__global__ __launch_bounds__(256, 2)
void gemm_tc(const float* __restrict__ A,
             const float* __restrict__ W0, const float* __restrict__ W1,
             const float* __restrict__ mu, const float* __restrict__ rs,
             const float* __restrict__ gamma, const float* __restrict__ beta,
             float* __restrict__ C0, float* __restrict__ C1,
             int K)
{
    // As: [mt(8)][ks(4)][lane(32)][reg(4)]  = 4096 u32
    // Bs: [nt(16)][ks(4)][lane(32)][reg(2)] = 4096 u32
    __shared__ unsigned As[4096];
    __shared__ unsigned Bs[4096];

    const int tid    = threadIdx.x;
    const int lane   = tid & 31;
    const int wid    = tid >> 5;
    const int warp_m = wid >> 2;      // 0..1
    const int warp_n = wid & 3;       // 0..3
    const int m0 = blockIdx.y * 128;
    const int n0 = blockIdx.x * 128;

    const float* Wp = W0;
    int wcol0 = n0;
    if (MODE == 0 && n0 >= 1024) { Wp = W1; wcol0 = n0 - 1024; }

    // A-load assignment: quad q = tid + it*256 (it 0..3); row = q>>3, k = (q&7)*4
    float a_mu[4], a_rs[4];
    int a_row[4];
#pragma unroll
    for (int it = 0; it < 4; it++) {
        a_row[it] = ((tid + it * 256) >> 3);
        if (MODE != 2) { a_mu[it] = mu[m0 + a_row[it]]; a_rs[it] = rs[m0 + a_row[it]]; }
        else           { a_mu[it] = 0.f; a_rs[it] = 1.f; }
    }

    float acc[4][4][4];
#pragma unroll
    for (int i = 0; i < 4; i++)
#pragma unroll
        for (int j = 0; j < 4; j++)
#pragma unroll
            for (int r = 0; r < 4; r++) acc[i][j][r] = 0.f;

    for (int k0 = 0; k0 < K; k0 += 32) {
        __syncthreads();
        // ---- A tile -> fragment-permuted smem (LN + tf32 cvt fused)
#pragma unroll
        for (int it = 0; it < 4; it++) {
            int quad = tid + it * 256;
            int row  = a_row[it];
            int k    = (quad & 7) << 2;          // 0,4,..28
            float4 v = *(const float4*)(A + (size_t)(m0 + row) * K + k0 + k);
            float vv[4] = {v.x, v.y, v.z, v.w};
            float gmv[4] = {1.f,1.f,1.f,1.f}, btv[4] = {0.f,0.f,0.f,0.f};
            if (MODE != 2) {
                float4 g4 = *(const float4*)(gamma + k0 + k);
                float4 b4 = *(const float4*)(beta  + k0 + k);
                gmv[0]=g4.x; gmv[1]=g4.y; gmv[2]=g4.z; gmv[3]=g4.w;
                btv[0]=b4.x; btv[1]=b4.y; btv[2]=b4.z; btv[3]=b4.w;
            }
            int mt   = row >> 4;
            int ks   = k >> 3;
            int base = ((mt * 4 + ks) * 32 + (row & 7) * 4) * 4 + ((row >> 3) & 1);
            int t4   = (k & 4) >> 1;             // reg bit1
#pragma unroll
            for (int u = 0; u < 4; u++) {
                float val = vv[u];
                if (MODE != 2) val = (val - a_mu[it]) * a_rs[it] * gmv[u] + btv[u];
                As[base + u * 4 + t4] = f2tf(val);
            }
        }
        // ---- B tile -> fragment-permuted smem
#pragma unroll
        for (int it = 0; it < 4; it++) {
            int quad = tid + it * 256;
            int k = quad >> 5;                   // 0..31
            int n = (quad & 31) << 2;            // 0,4,..124
            float4 w = *(const float4*)(Wp + (size_t)(k0 + k) * 1024 + wcol0 + n);
            float wv[4] = {w.x, w.y, w.z, w.w};
            int nt = n >> 3, ks = k >> 3, reg = (k & 4) >> 2;
#pragma unroll
            for (int u = 0; u < 4; u++) {
                int addr = (((nt * 4 + ks) * 32) + ((n & 7) + u) * 4 + (k & 3)) * 2 + reg;
                Bs[addr] = f2tf(wv[u]);
            }
        }
        __syncthreads();

        // ---- compute: 4 k-steps x 4x4 mma
#pragma unroll
        for (int ks = 0; ks < 4; ks++) {
            unsigned af[4][4];
            unsigned bf[4][2];
#pragma unroll
            for (int i = 0; i < 4; i++) {
                uint4 a4 = *(const uint4*)&As[(((warp_m * 4 + i) * 4 + ks) * 32 + lane) * 4];
                af[i][0]=a4.x; af[i][1]=a4.y; af[i][2]=a4.z; af[i][3]=a4.w;
            }
#pragma unroll
            for (int j = 0; j < 4; j++) {
                uint2 b2 = *(const uint2*)&Bs[(((warp_n * 4 + j) * 4 + ks) * 32 + lane) * 2];
                bf[j][0]=b2.x; bf[j][1]=b2.y;
            }
#pragma unroll
            for (int i = 0; i < 4; i++)
#pragma unroll
                for (int j = 0; j < 4; j++)
                    mma_tf32(acc[i][j], af[i], bf[j]);
        }
    }

    // ---- store (fragment -> global scatter)
    const int g = lane >> 2, t = lane & 3;
#pragma unroll
    for (int i = 0; i < 4; i++) {
#pragma unroll
        for (int j = 0; j < 4; j++) {
#pragma unroll
            for (int cr = 0; cr < 4; cr++) {
                int r = m0 + warp_m * 64 + i * 16 + g + ((cr & 2) ? 8 : 0);
                int c = n0 + warp_n * 32 + j * 8 + 2 * t + (cr & 1);
                float v = acc[i][j][cr];
                if (MODE == 0) {
                    int part = c >> 10, cc = c & 1023;
                    int h = cc >> 7, d = cc & 127;
                    int bb = r >> 14, l = r & 16383;
                    float* dst = part ? C1 : C0;
                    dst[(((size_t)(bb * 8 + h) << 14) + l) * 128 + d] = v;
                } else if (MODE == 1) {
                    int h = c >> 7, d = c & 127;
                    int bb = r >> 9, q = r & 511;
                    C0[(((size_t)(bb * 8 + h)) * 512 + q) * 128 + d] = 0.08838834764831845f * v;
                } else {
                    C0[(size_t)r * 1024 + c] = v;
                }
            }
        }
    }
}

// ---------------------------------------------------------------------------
// Tensor-core flash attention. Br=128, Bc=64, d=128, 256 threads (8 warps).
// Warp w owns Q rows w*16..w*16+15 (full rows -> softmax reduces over 4 lanes).
// Smem (tf32 bits unless noted):
//   Qs [w*16+ks][lane][4]           : 8*16*32*4  = 16384 u32 (64KB)
//   Ks [nt(8)][ks(16)][lane][2]     : 8192 u32 (32KB)
//   Vs [nt(16)][ks(8)][lane][2]     : 8192 u32 (32KB)
//   Ps per warp [16][68] float      : 8704 f32 (34KB)
// ---------------------------------------------------------------------------
#define ATTN_SMEM_WORDS (16384 + 8192 + 8192 + 8704)
#define ATTN_SMEM_BYTES (ATTN_SMEM_WORDS * 4)

__global__ __launch_bounds__(256, 1)
void attn_tc(const float* __restrict__ Qb, const float* __restrict__ Kb,
             const float* __restrict__ Vb, float* __restrict__ AO)
{
    extern __shared__ unsigned smu[];
    unsigned* Qs = smu;
    unsigned* Ks = smu + 16384;
    unsigned* Vs = smu + 24576;
    float*    Ps = (float*)(smu + 32768);

    const int tid  = threadIdx.x;
    const int lane = tid & 31;
    const int w    = tid >> 5;
    const int g    = lane >> 2, t = lane & 3;
    const int bh   = blockIdx.y;
    const int q0   = blockIdx.x * 128;

    const float* Qg = Qb + ((size_t)bh * LQ + q0) * DH;
    const float* Kg = Kb + (size_t)bh * LKV * DH;
    const float* Vg = Vb + (size_t)bh * LKV * DH;

    // ---- load Q tile into fragment-permuted smem (tf32)
#pragma unroll
    for (int it = 0; it < 16; it++) {
        int quad = tid + it * 256;
        int q = quad >> 5;
        int d = (quad & 31) << 2;
        float4 v = *(const float4*)(Qg + (size_t)q * 128 + d);
        float vv[4] = {v.x, v.y, v.z, v.w};
        int wq = q >> 4, r = q & 15, ks = d >> 3;
        int base = (wq * 16 + ks) * 128 + (r & 7) * 16;      // lane*4 with lane=(r&7)*4+u
        int reg  = ((d & 4) >> 1) | ((r >> 3) & 1);
#pragma unroll
        for (int u = 0; u < 4; u++)
            Qs[base + u * 4 + reg] = f2tf(vv[u]);
    }

    float accO[16][4];
    float rowm0 = -1e30f, rowm1 = -1e30f, rowl0 = 0.f, rowl1 = 0.f;
#pragma unroll
    for (int nt = 0; nt < 16; nt++)
#pragma unroll
        for (int c = 0; c < 4; c++) accO[nt][c] = 0.f;

    float* Ps_w = Ps + w * (16 * 68);

    for (int c0 = 0; c0 < LKV; c0 += 64) {
        __syncthreads();   // prev-iter Ks/Vs readers done (covers Qs on iter 0)
        // ---- load K and V chunks (fragment-permuted, tf32)
#pragma unroll
        for (int it = 0; it < 8; it++) {
            int quad = tid + it * 256;
            int l = quad >> 5;
            int d = (quad & 31) << 2;
            float4 kv = *(const float4*)(Kg + (size_t)(c0 + l) * 128 + d);
            float4 vv = *(const float4*)(Vg + (size_t)(c0 + l) * 128 + d);
            float kk[4] = {kv.x, kv.y, kv.z, kv.w};
            float vf[4] = {vv.x, vv.y, vv.z, vv.w};
            // K: B-frag of S-mma: nt=l>>3, ks=d>>3, lane=(l&7)*4+u', reg=(d&4)>>2
            {
                int nt = l >> 3, ks = d >> 3, reg = (d & 4) >> 2;
                int base = ((nt * 16 + ks) * 32 + (l & 7) * 4);
#pragma unroll
                for (int u = 0; u < 4; u++)
                    Ks[(base + u) * 2 + reg] = f2tf(kk[u]);
            }
            // V: B-frag of PV-mma: nt=d>>3, ks=l>>3, lane=((d&7)+u)*4+(l&3), reg=(l&4)>>2
            {
                int nt = d >> 3, ks = l >> 3, reg = (l & 4) >> 2;
#pragma unroll
                for (int u = 0; u < 4; u++) {
                    int ln = ((d & 7) + u) * 4 + (l & 3);
                    Vs[((nt * 8 + ks) * 32 + ln) * 2 + reg] = f2tf(vf[u]);
                }
            }
        }
        __syncthreads();

        // ---- S = Q K^T : per warp 16x64, 8 n-tiles x 16 k-steps
        float s[8][4];
#pragma unroll
        for (int nt = 0; nt < 8; nt++)
#pragma unroll
            for (int c = 0; c < 4; c++) s[nt][c] = 0.f;

#pragma unroll
        for (int ks = 0; ks < 16; ks++) {
            uint4 a4 = *(const uint4*)&Qs[(w * 16 + ks) * 128 + lane * 4];
            unsigned af[4] = {a4.x, a4.y, a4.z, a4.w};
#pragma unroll
            for (int nt = 0; nt < 8; nt++) {
                uint2 b2 = *(const uint2*)&Ks[((nt * 16 + ks) * 32 + lane) * 2];
                unsigned bf[2] = {b2.x, b2.y};
                mma_tf32(s[nt], af, bf);
            }
        }

        // ---- online softmax (rows g and g+8; reduce over lanes t=0..3)
        float m0 = -1e30f, m1 = -1e30f;
#pragma unroll
        for (int nt = 0; nt < 8; nt++) {
            m0 = fmaxf(m0, fmaxf(s[nt][0], s[nt][1]));
            m1 = fmaxf(m1, fmaxf(s[nt][2], s[nt][3]));
        }
#pragma unroll
        for (int o = 1; o <= 2; o <<= 1) {
            m0 = fmaxf(m0, __shfl_xor_sync(0xffffffffu, m0, o));
            m1 = fmaxf(m1, __shfl_xor_sync(0xffffffffu, m1, o));
        }
        float mn0 = fmaxf(rowm0, m0), mn1 = fmaxf(rowm1, m1);
        float f0 = __expf(rowm0 - mn0), f1 = __expf(rowm1 - mn1);
        rowm0 = mn0; rowm1 = mn1;

        float ls0 = 0.f, ls1 = 0.f;
#pragma unroll
        for (int nt = 0; nt < 8; nt++) {
            s[nt][0] = __expf(s[nt][0] - mn0);
            s[nt][1] = __expf(s[nt][1] - mn0);
            s[nt][2] = __expf(s[nt][2] - mn1);
            s[nt][3] = __expf(s[nt][3] - mn1);
            ls0 += s[nt][0] + s[nt][1];
            ls1 += s[nt][2] + s[nt][3];
        }
#pragma unroll
        for (int o = 1; o <= 2; o <<= 1) {
            ls0 += __shfl_xor_sync(0xffffffffu, ls0, o);
            ls1 += __shfl_xor_sync(0xffffffffu, ls1, o);
        }
        rowl0 = rowl0 * f0 + ls0;
        rowl1 = rowl1 * f1 + ls1;

#pragma unroll
        for (int nt = 0; nt < 16; nt++) {
            accO[nt][0] *= f0; accO[nt][1] *= f0;
            accO[nt][2] *= f1; accO[nt][3] *= f1;
        }

        // ---- P -> per-warp smem (tf32 bits stored as float), re-fragment
#pragma unroll
        for (int nt = 0; nt < 8; nt++) {
            int cb = nt * 8 + 2 * t;
            Ps_w[g * 68 + cb]           = __uint_as_float(f2tf(s[nt][0]));
            Ps_w[g * 68 + cb + 1]       = __uint_as_float(f2tf(s[nt][1]));
            Ps_w[(g + 8) * 68 + cb]     = __uint_as_float(f2tf(s[nt][2]));
            Ps_w[(g + 8) * 68 + cb + 1] = __uint_as_float(f2tf(s[nt][3]));
        }
        __syncwarp();

        // ---- O += P @ V : 16 n-tiles x 8 k-steps
#pragma unroll
        for (int ks = 0; ks < 8; ks++) {
            unsigned af[4];
            af[0] = __float_as_uint(Ps_w[g * 68 + ks * 8 + t]);
            af[1] = __float_as_uint(Ps_w[(g + 8) * 68 + ks * 8 + t]);
            af[2] = __float_as_uint(Ps_w[g * 68 + ks * 8 + t + 4]);
            af[3] = __float_as_uint(Ps_w[(g + 8) * 68 + ks * 8 + t + 4]);
#pragma unroll
            for (int nt = 0; nt < 16; nt++) {
                uint2 b2 = *(const uint2*)&Vs[((nt * 8 + ks) * 32 + lane) * 2];
                unsigned bf[2] = {b2.x, b2.y};
                mma_tf32(accO[nt], af, bf);
            }
        }
        __syncwarp();   // Ps reads done before next iter's stores
    }

    // ---- epilogue: normalize, scatter to [b*512+q][h*128+d]
    int bb = bh >> 3, h = bh & 7;
    float inv0 = 1.f / rowl0, inv1 = 1.f / rowl1;
    int r0 = q0 + w * 16 + g;
#pragma unroll
    for (int nt = 0; nt < 16; nt++) {
        int d = nt * 8 + 2 * t;
        size_t o0 = ((size_t)(bb * 512 + r0)) * 1024 + h * 128 + d;
        size_t o1 = ((size_t)(bb * 512 + r0 + 8)) * 1024 + h * 128 + d;
        AO[o0]     = accO[nt][0] * inv0;
        AO[o0 + 1] = accO[nt][1] * inv0;
        AO[o1]     = accO[nt][2] * inv1;
        AO[o1 + 1] = accO[nt][3] * inv1;
    }
}

// ---------------------------------------------------------------------------
// Launcher (graph-capturable: kernel launches only)
// ---------------------------------------------------------------------------
extern "C" void kernel_launch(void* const* d_in, const int* in_sizes, int n_in,
                              void* d_out, int out_size)
{
    (void)in_sizes; (void)n_in; (void)out_size;
    const float* latent   = (const float*)d_in[0];
    const float* inpkv    = (const float*)d_in[1];
    const float* W_Q      = (const float*)d_in[2];
    const float* W_K      = (const float*)d_in[3];
    const float* W_V      = (const float*)d_in[4];
    const float* W_O      = (const float*)d_in[5];
    const float* ln_lat_g = (const float*)d_in[6];
    const float* ln_lat_b = (const float*)d_in[7];
    const float* ln_in_g  = (const float*)d_in[8];
    const float* ln_in_b  = (const float*)d_in[9];
    float* out = (float*)d_out;

    float *p_mukv, *p_rskv, *p_muq, *p_rsq, *p_Q, *p_K, *p_V, *p_AO;
    cudaGetSymbolAddress((void**)&p_mukv, g_mu_kv);
    cudaGetSymbolAddress((void**)&p_rskv, g_rs_kv);
    cudaGetSymbolAddress((void**)&p_muq,  g_mu_q);
    cudaGetSymbolAddress((void**)&p_rsq,  g_rs_q);
    cudaGetSymbolAddress((void**)&p_Q,    g_Qb);
    cudaGetSymbolAddress((void**)&p_K,    g_Kb);
    cudaGetSymbolAddress((void**)&p_V,    g_Vb);
    cudaGetSymbolAddress((void**)&p_AO,   g_AO);

    cudaFuncSetAttribute(attn_tc, cudaFuncAttributeMaxDynamicSharedMemorySize,
                         ATTN_SMEM_BYTES);

    // LN row statistics
    rowstats_kernel<<<MKV / 8, 256>>>(inpkv,  p_mukv, p_rskv, CH_IN);
    rowstats_kernel<<<MQ  / 8, 256>>>(latent, p_muq,  p_rsq,  CH_LAT);

    // Q projection (LN fused, softmax scale folded)
    gemm_tc<1><<<dim3(8, MQ / 128), 256>>>(latent, W_Q, nullptr,
                                           p_muq, p_rsq, ln_lat_g, ln_lat_b,
                                           p_Q, nullptr, CH_LAT);
    // K|V projection (LN fused, one pass over input_kv)
    gemm_tc<0><<<dim3(16, MKV / 128), 256>>>(inpkv, W_K, W_V,
                                             p_mukv, p_rskv, ln_in_g, ln_in_b,
                                             p_K, p_V, CH_IN);
    // flash attention (tensor core)
    attn_tc<<<dim3(4, BH), 256, ATTN_SMEM_BYTES>>>(p_Q, p_K, p_V, p_AO);

    // output projection
    gemm_tc<2><<<dim3(8, MQ / 128), 256>>>(p_AO, W_O, nullptr,
                                           nullptr, nullptr, nullptr, nullptr,
                                           out, nullptr, 1024);
}

// round 5
// speedup vs baseline: 2.9187x; 2.3815x over previous
#include <cuda_runtime.h>
#include <math.h>
#include <stdint.h>

// ---------------------------------------------------------------------------
// Problem dims
// ---------------------------------------------------------------------------
#define NB      8
#define LQ      512
#define LKV     16384
#define CH_LAT  1024
#define CH_IN   768
#define DH      128
#define NH      8
#define BH      (NB*NH)        // 64
#define MKV     (NB*LKV)       // 131072
#define MQ      (NB*LQ)        // 4096

// 1/sqrt(128) * log2(e)  (Q pre-scale; softmax uses exp2)
#define QSCALE  (0.08838834764831845f * 1.4426950408889634f)

// ---------------------------------------------------------------------------
// Scratch (device globals -- no allocations allowed)
// ---------------------------------------------------------------------------
__device__ float g_mu_kv[MKV];
__device__ float g_rs_kv[MKV];
__device__ float g_mu_q[MQ];
__device__ float g_rs_q[MQ];
__device__ float g_Qb[(size_t)BH*LQ*DH];     // [bh][q][d], scaled by QSCALE
__device__ float g_Kb[(size_t)BH*LKV*DH];    // [bh][l][d]
__device__ float g_Vb[(size_t)BH*LKV*DH];    // [bh][l][d]
__device__ float g_Vt[(size_t)BH*DH*LKV];    // [bh][d][l]
__device__ float g_AO[(size_t)MQ*1024];      // [b*512+q][h*128+d]
__device__ float g_WTkv[2048*768];           // n-major: rows 0..1023 = W_K^T, 1024.. = W_V^T
__device__ float g_WTq[1024*1024];
__device__ float g_WTo[1024*1024];

// ---------------------------------------------------------------------------
// tf32 helpers (baseline PTX only -- tcgen05 is rejected by this toolchain)
// ---------------------------------------------------------------------------
__device__ __forceinline__ unsigned f2tf(float x) {
    unsigned r; asm("cvt.rna.tf32.f32 %0, %1;" : "=r"(r) : "f"(x)); return r;
}
__device__ __forceinline__ void mma_tf32(float* c, const unsigned* a, const unsigned* b) {
    asm volatile(
        "mma.sync.aligned.m16n8k8.row.col.f32.tf32.tf32.f32 "
        "{%0,%1,%2,%3}, {%4,%5,%6,%7}, {%8,%9}, {%0,%1,%2,%3};\n"
        : "+f"(c[0]), "+f"(c[1]), "+f"(c[2]), "+f"(c[3])
        : "r"(a[0]), "r"(a[1]), "r"(a[2]), "r"(a[3]), "r"(b[0]), "r"(b[1]));
}

// Swizzled smem offsets (word units). Rows of 32/128/64 floats; the f4 column
// index is XORed with low row bits -> conflict-free STS.128 staging AND
// conflict-free LDS.32 fragment loads (banks (f4'^g)*4+t span all 32).
__device__ __forceinline__ int sw32(int row, int k) {   // 32-float rows
    return row * 32 + ((((k >> 2) ^ row) & 7) << 2) + (k & 3);
}
__device__ __forceinline__ int sw128r(int row, int k) { // 128-float rows
    return row * 128 + ((((k >> 2) ^ row) & 31) << 2) + (k & 3);
}
__device__ __forceinline__ int sw64v(int row, int k) {  // 64-float rows (V)
    return row * 64 + ((((k >> 2) ^ row) & 15) << 2) + (k & 3);
}
__device__ __forceinline__ int sw64p(int row, int k) {  // 64-float rows (P), parity-rotated
    return row * 64 + (((((((k >> 2) ^ row) & 15)) << 2) + (k & 3) + ((row & 1) << 4)) & 63);
}

// ---------------------------------------------------------------------------
// Row stats for LayerNorm (one warp per row)
// ---------------------------------------------------------------------------
__global__ void rowstats_kernel(const float* __restrict__ X, float* __restrict__ mu,
                                float* __restrict__ rs, int cols)
{
    int row  = blockIdx.x * 8 + (threadIdx.x >> 5);
    int lane = threadIdx.x & 31;
    const float* xr = X + (size_t)row * cols;
    float s = 0.f, s2 = 0.f;
    for (int c = lane; c < cols; c += 32) { float v = xr[c]; s += v; s2 += v * v; }
#pragma unroll
    for (int o = 16; o; o >>= 1) {
        s  += __shfl_xor_sync(0xffffffffu, s,  o);
        s2 += __shfl_xor_sync(0xffffffffu, s2, o);
    }
    if (lane == 0) {
        float m = s / cols;
        float var = fmaxf(s2 / cols - m * m, 0.f);
        mu[row] = m; rs[row] = rsqrtf(var + 1e-5f);
    }
}

// ---------------------------------------------------------------------------
// Batched transpose: out[z][c][r] = in[z][r][c]
// ---------------------------------------------------------------------------
__global__ void transpose_kernel(const float* __restrict__ in, float* __restrict__ out,
                                 int R, int C)
{
    __shared__ float t[32][33];
    int c0 = blockIdx.x * 32, r0 = blockIdx.y * 32;
    size_t zoff = (size_t)blockIdx.z * R * C;
    int tx = threadIdx.x, ty = threadIdx.y;
#pragma unroll
    for (int j = 0; j < 4; j++)
        t[ty + j * 8][tx] = in[zoff + (size_t)(r0 + ty + j * 8) * C + c0 + tx];
    __syncthreads();
#pragma unroll
    for (int j = 0; j < 4; j++)
        out[zoff + (size_t)(c0 + ty + j * 8) * R + r0 + tx] = t[tx][ty + j * 8];
}

// ---------------------------------------------------------------------------
// TF32 mma.sync GEMM: block 128x128, BK=32, 256 threads (8 warps 2x4),
// warp tile 64x32 (4x4 m16n8k8). Natural-layout swizzled staging,
// double-buffered smem, global prefetch. LN fused into A (MODE 0/1).
// MODE 0: A=input_kv, B=g_WTkv (N=2048) -> scatter g_Kb/g_Vb
// MODE 1: A=latent,   B=g_WTq          -> g_Qb (QSCALE folded)
// MODE 2: A=g_AO,     B=g_WTo          -> row-major out
// ---------------------------------------------------------------------------
#define G_SMEM_WORDS 16384     // As[2][4096] + Bs[2][4096]
#define G_SMEM_BYTES (G_SMEM_WORDS*4)

template<int MODE>
__global__ __launch_bounds__(256, 1)
void gemm_tc(const float* __restrict__ A, const float* __restrict__ WT,
             const float* __restrict__ mu, const float* __restrict__ rs,
             const float* __restrict__ gamma, const float* __restrict__ beta,
             float* __restrict__ C, int K)
{
    extern __shared__ unsigned smu[];
    unsigned* As = smu;             // [2][128*32]
    unsigned* Bs = smu + 8192;      // [2][128*32]

    const int tid = threadIdx.x;
    const int lane = tid & 31, wid = tid >> 5;
    const int wm = wid >> 2, wn = wid & 3;
    const int g = lane >> 2, t = lane & 3;
    const int m0 = blockIdx.y * 128, n0 = blockIdx.x * 128;
    const int KC = K >> 5;

    const int arow = tid >> 3;      // base row; +32 per it
    const int af4  = tid & 7;       // f4-column within 32-float row

    const float* Ab = A  + (size_t)(m0 + arow) * K + af4 * 4;
    const float* Bb = WT + (size_t)(n0 + arow) * K + af4 * 4;

    float mu4[4], rs4[4];
#pragma unroll
    for (int it = 0; it < 4; it++) {
        if (MODE != 2) { mu4[it] = mu[m0 + arow + it * 32]; rs4[it] = rs[m0 + arow + it * 32]; }
        else           { mu4[it] = 0.f; rs4[it] = 1.f; }
    }

    float acc[4][4][4];
#pragma unroll
    for (int i = 0; i < 4; i++)
#pragma unroll
        for (int j = 0; j < 4; j++)
#pragma unroll
            for (int r = 0; r < 4; r++) acc[i][j][r] = 0.f;

    float4 ar[4], br[4], gm4, bt4;
    // prefetch chunk 0
#pragma unroll
    for (int it = 0; it < 4; it++) {
        ar[it] = *(const float4*)(Ab + (size_t)it * 32 * K);
        br[it] = *(const float4*)(Bb + (size_t)it * 32 * K);
    }
    if (MODE != 2) { gm4 = *(const float4*)(gamma + af4 * 4); bt4 = *(const float4*)(beta + af4 * 4); }

    for (int c = 0; c < KC; c++) {
        unsigned* ab = As + (c & 1) * 4096;
        unsigned* bb = Bs + (c & 1) * 4096;
        // ---- store staged regs -> smem (swizzled, conflict-free)
#pragma unroll
        for (int it = 0; it < 4; it++) {
            int row = arow + it * 32;
            float4 v = ar[it];
            if (MODE != 2) {
                v.x = (v.x - mu4[it]) * rs4[it] * gm4.x + bt4.x;
                v.y = (v.y - mu4[it]) * rs4[it] * gm4.y + bt4.y;
                v.z = (v.z - mu4[it]) * rs4[it] * gm4.z + bt4.z;
                v.w = (v.w - mu4[it]) * rs4[it] * gm4.w + bt4.w;
            }
            uint4 u; u.x = f2tf(v.x); u.y = f2tf(v.y); u.z = f2tf(v.z); u.w = f2tf(v.w);
            *(uint4*)&ab[sw32(row, af4 * 4)] = u;
            float4 w = br[it];
            uint4 uw; uw.x = f2tf(w.x); uw.y = f2tf(w.y); uw.z = f2tf(w.z); uw.w = f2tf(w.w);
            *(uint4*)&bb[sw32(row, af4 * 4)] = uw;
        }
        __syncthreads();
        // ---- prefetch next chunk
        if (c + 1 < KC) {
            int k0 = (c + 1) * 32;
#pragma unroll
            for (int it = 0; it < 4; it++) {
                ar[it] = *(const float4*)(Ab + (size_t)it * 32 * K + k0);
                br[it] = *(const float4*)(Bb + (size_t)it * 32 * K + k0);
            }
            if (MODE != 2) {
                gm4 = *(const float4*)(gamma + k0 + af4 * 4);
                bt4 = *(const float4*)(beta  + k0 + af4 * 4);
            }
        }
        // ---- compute
#pragma unroll
        for (int ks = 0; ks < 4; ks++) {
            unsigned afr[4][4], bfr[4][2];
            int kk = ks * 8 + t;
#pragma unroll
            for (int i = 0; i < 4; i++) {
                int m = wm * 64 + i * 16 + g;
                afr[i][0] = ab[sw32(m,     kk)];
                afr[i][1] = ab[sw32(m + 8, kk)];
                afr[i][2] = ab[sw32(m,     kk + 4)];
                afr[i][3] = ab[sw32(m + 8, kk + 4)];
            }
#pragma unroll
            for (int j = 0; j < 4; j++) {
                int n = wn * 32 + j * 8 + g;
                bfr[j][0] = bb[sw32(n, kk)];
                bfr[j][1] = bb[sw32(n, kk + 4)];
            }
#pragma unroll
            for (int i = 0; i < 4; i++)
#pragma unroll
                for (int j = 0; j < 4; j++)
                    mma_tf32(acc[i][j], afr[i], bfr[j]);
        }
        // single sync per iter is sufficient with 2 buffers (see analysis)
    }

    // ---- epilogue (store float2 pairs from C-frags)
#pragma unroll
    for (int i = 0; i < 4; i++) {
#pragma unroll
        for (int j = 0; j < 4; j++) {
#pragma unroll
            for (int half = 0; half < 2; half++) {
                int r = m0 + wm * 64 + i * 16 + g + half * 8;
                int cc = n0 + wn * 32 + j * 8 + 2 * t;
                float v0 = acc[i][j][half * 2 + 0];
                float v1 = acc[i][j][half * 2 + 1];
                if (MODE == 0) {
                    int part = cc >> 10, c2 = cc & 1023;
                    int h = c2 >> 7, d = c2 & 127;
                    int bb2 = r >> 14, l = r & 16383;
                    float* dst = (part ? g_Vb : g_Kb)
                               + ((((size_t)(bb2 * 8 + h)) << 14) + l) * 128 + d;
                    *(float2*)dst = make_float2(v0, v1);
                } else if (MODE == 1) {
                    int h = cc >> 7, d = cc & 127;
                    int bb2 = r >> 9, q = r & 511;
                    float* dst = g_Qb + (((size_t)(bb2 * 8 + h)) * 512 + q) * 128 + d;
                    *(float2*)dst = make_float2(QSCALE * v0, QSCALE * v1);
                } else {
                    *(float2*)(C + (size_t)r * 1024 + cc) = make_float2(v0, v1);
                }
            }
        }
    }
}

// ---------------------------------------------------------------------------
// TF32 mma.sync flash attention, max-free softmax (exp2, scale pre-folded).
// Br=128, Bc=64, d=128, 256 threads (8 warps).
// S phase:  warps 4x2 (q 32 x l 32): warp tile 32x32 (2x4 tiles), ks=16.
// PV phase: warps 2x4 (q 64 x d 32): warp tile 64x32 (4x4 tiles), ks=8.
// Smem (words): Qs 16384 | Ks 8192 | Vs 8192 | Ps 8192 | ls 256.
// Row sums accumulate in registers across all chunks; one reduction at end.
// ---------------------------------------------------------------------------
#define AQ_OFF  0
#define AK_OFF  16384
#define AV_OFF  24576
#define AP_OFF  32768
#define ALS_OFF 40960
#define A_SMEM_WORDS 41216
#define A_SMEM_BYTES (A_SMEM_WORDS*4)

__global__ __launch_bounds__(256, 1)
void attn_tc(const float* __restrict__ Qb, const float* __restrict__ Kb,
             const float* __restrict__ Vt, float* __restrict__ AO)
{
    extern __shared__ unsigned smu[];
    unsigned* Qs = smu + AQ_OFF;
    unsigned* Ks = smu + AK_OFF;
    unsigned* Vs = smu + AV_OFF;
    unsigned* Ps = smu + AP_OFF;
    float*    ls = (float*)(smu + ALS_OFF);

    const int tid = threadIdx.x;
    const int lane = tid & 31, wid = tid >> 5;
    const int g = lane >> 2, t = lane & 3;
    const int bh = blockIdx.y;
    const int q0 = blockIdx.x * 128;

    const int wq4 = wid & 3,  wl = wid >> 2;   // S-phase split (q 32, l 32)
    const int wq2 = wid & 1,  wd = wid >> 1;   // PV-phase split (q 64, d 32)

    const float* Qg = Qb + ((size_t)bh * LQ + q0) * DH;
    const float* Kg = Kb + (size_t)bh * LKV * DH;
    const float* Vg = Vt + (size_t)bh * DH * LKV;

    // ---- stage Q once (tf32, swizzled)
#pragma unroll
    for (int it = 0; it < 16; it++) {
        int idx = tid + it * 256;
        int row = idx >> 5, f4 = idx & 31;
        float4 v = *(const float4*)(Qg + (size_t)row * 128 + f4 * 4);
        uint4 u; u.x = f2tf(v.x); u.y = f2tf(v.y); u.z = f2tf(v.z); u.w = f2tf(v.w);
        *(uint4*)&Qs[sw128r(row, f4 * 4)] = u;
    }

    float oacc[4][4][4];
#pragma unroll
    for (int i = 0; i < 4; i++)
#pragma unroll
        for (int j = 0; j < 4; j++)
#pragma unroll
            for (int r = 0; r < 4; r++) oacc[i][j][r] = 0.f;
    float rsum[2][2] = {{0.f, 0.f}, {0.f, 0.f}};

    for (int ci = 0; ci < LKV / 64; ci++) {
        int c0 = ci * 64;
        __syncthreads();   // prev PV readers done (Vs/Ps free); covers Q on ci=0
        // ---- stage K (64 x 128) and V^T slice (128 x 64)
#pragma unroll
        for (int it = 0; it < 8; it++) {
            int idx = tid + it * 256;
            int row = idx >> 5, f4 = idx & 31;
            float4 v = *(const float4*)(Kg + (size_t)(c0 + row) * 128 + f4 * 4);
            uint4 u; u.x = f2tf(v.x); u.y = f2tf(v.y); u.z = f2tf(v.z); u.w = f2tf(v.w);
            *(uint4*)&Ks[sw128r(row, f4 * 4)] = u;
        }
#pragma unroll
        for (int it = 0; it < 8; it++) {
            int idx = tid + it * 256;
            int d = idx >> 4, f4 = idx & 15;
            float4 v = *(const float4*)(Vg + (size_t)d * LKV + c0 + f4 * 4);
            uint4 u; u.x = f2tf(v.x); u.y = f2tf(v.y); u.z = f2tf(v.z); u.w = f2tf(v.w);
            *(uint4*)&Vs[sw64v(d, f4 * 4)] = u;
        }
        __syncthreads();

        // ---- S = Q K^T (warp tile 32 q x 32 l)
        float sac[2][4][4];
#pragma unroll
        for (int i = 0; i < 2; i++)
#pragma unroll
            for (int j = 0; j < 4; j++)
#pragma unroll
                for (int r = 0; r < 4; r++) sac[i][j][r] = 0.f;

#pragma unroll
        for (int ks = 0; ks < 16; ks++) {
            int kk = ks * 8 + t;
            unsigned afr[2][4], bfr[4][2];
#pragma unroll
            for (int i = 0; i < 2; i++) {
                int m = wq4 * 32 + i * 16 + g;
                afr[i][0] = Qs[sw128r(m,     kk)];
                afr[i][1] = Qs[sw128r(m + 8, kk)];
                afr[i][2] = Qs[sw128r(m,     kk + 4)];
                afr[i][3] = Qs[sw128r(m + 8, kk + 4)];
            }
#pragma unroll
            for (int j = 0; j < 4; j++) {
                int n = wl * 32 + j * 8 + g;
                bfr[j][0] = Ks[sw128r(n, kk)];
                bfr[j][1] = Ks[sw128r(n, kk + 4)];
            }
#pragma unroll
            for (int i = 0; i < 2; i++)
#pragma unroll
                for (int j = 0; j < 4; j++)
                    mma_tf32(sac[i][j], afr[i], bfr[j]);
        }

        // ---- P = exp2(S); accumulate row sums; write P (swizzled, parity-rotated)
#pragma unroll
        for (int i = 0; i < 2; i++) {
            int r0 = wq4 * 32 + i * 16 + g;
#pragma unroll
            for (int j = 0; j < 4; j++) {
                int cc = wl * 32 + j * 8 + 2 * t;
                float p0 = exp2f(sac[i][j][0]);
                float p1 = exp2f(sac[i][j][1]);
                float p2 = exp2f(sac[i][j][2]);
                float p3 = exp2f(sac[i][j][3]);
                rsum[i][0] += p0 + p1;
                rsum[i][1] += p2 + p3;
                uint2 u0; u0.x = f2tf(p0); u0.y = f2tf(p1);
                uint2 u1; u1.x = f2tf(p2); u1.y = f2tf(p3);
                *(uint2*)&Ps[sw64p(r0,     cc)] = u0;
                *(uint2*)&Ps[sw64p(r0 + 8, cc)] = u1;
            }
        }
        __syncthreads();

        // ---- O += P V (warp tile 64 q x 32 d)
#pragma unroll
        for (int ks = 0; ks < 8; ks++) {
            int kk = ks * 8 + t;
            unsigned afr[4][4], bfr[4][2];
#pragma unroll
            for (int i = 0; i < 4; i++) {
                int m = wq2 * 64 + i * 16 + g;
                afr[i][0] = Ps[sw64p(m,     kk)];
                afr[i][1] = Ps[sw64p(m + 8, kk)];
                afr[i][2] = Ps[sw64p(m,     kk + 4)];
                afr[i][3] = Ps[sw64p(m + 8, kk + 4)];
            }
#pragma unroll
            for (int j = 0; j < 4; j++) {
                int n = wd * 32 + j * 8 + g;
                bfr[j][0] = Vs[sw64v(n, kk)];
                bfr[j][1] = Vs[sw64v(n, kk + 4)];
            }
#pragma unroll
            for (int i = 0; i < 4; i++)
#pragma unroll
                for (int j = 0; j < 4; j++)
                    mma_tf32(oacc[i][j], afr[i], bfr[j]);
        }
    }

    // ---- row-sum reduction: quad (over t), then across wl via smem
#pragma unroll
    for (int i = 0; i < 2; i++)
#pragma unroll
        for (int h = 0; h < 2; h++) {
            float v = rsum[i][h];
            v += __shfl_xor_sync(0xffffffffu, v, 1);
            v += __shfl_xor_sync(0xffffffffu, v, 2);
            rsum[i][h] = v;
        }
    __syncthreads();            // Ps/Vs readers done; reuse ls region safely
    if (t == 0) {
#pragma unroll
        for (int i = 0; i < 2; i++) {
            int r = wq4 * 32 + i * 16 + g;
            ls[wl * 128 + r]     = rsum[i][0];
            ls[wl * 128 + r + 8] = rsum[i][1];
        }
    }
    __syncthreads();

    // ---- epilogue: normalize, scatter
    int bb2 = bh >> 3, h = bh & 7;
#pragma unroll
    for (int i = 0; i < 4; i++) {
#pragma unroll
        for (int half = 0; half < 2; half++) {
            int r = wq2 * 64 + i * 16 + g + half * 8;
            float inv = 1.f / (ls[r] + ls[128 + r]);
            size_t rowoff = ((size_t)(bb2 * 512 + q0 + r)) * 1024 + h * 128;
#pragma unroll
            for (int j = 0; j < 4; j++) {
                int cc = wd * 32 + j * 8 + 2 * t;
                *(float2*)(AO + rowoff + cc) =
                    make_float2(oacc[i][j][half * 2] * inv, oacc[i][j][half * 2 + 1] * inv);
            }
        }
    }
}

// ---------------------------------------------------------------------------
// Launcher (graph-capturable: kernel launches only)
// ---------------------------------------------------------------------------
extern "C" void kernel_launch(void* const* d_in, const int* in_sizes, int n_in,
                              void* d_out, int out_size)
{
    (void)in_sizes; (void)n_in; (void)out_size;
    const float* latent   = (const float*)d_in[0];
    const float* inpkv    = (const float*)d_in[1];
    const float* W_Q      = (const float*)d_in[2];
    const float* W_K      = (const float*)d_in[3];
    const float* W_V      = (const float*)d_in[4];
    const float* W_O      = (const float*)d_in[5];
    const float* ln_lat_g = (const float*)d_in[6];
    const float* ln_lat_b = (const float*)d_in[7];
    const float* ln_in_g  = (const float*)d_in[8];
    const float* ln_in_b  = (const float*)d_in[9];
    float* out = (float*)d_out;

    float *p_mukv, *p_rskv, *p_muq, *p_rsq, *p_Q, *p_K, *p_V, *p_Vt, *p_AO;
    float *p_WTkv, *p_WTq, *p_WTo;
    cudaGetSymbolAddress((void**)&p_mukv, g_mu_kv);
    cudaGetSymbolAddress((void**)&p_rskv, g_rs_kv);
    cudaGetSymbolAddress((void**)&p_muq,  g_mu_q);
    cudaGetSymbolAddress((void**)&p_rsq,  g_rs_q);
    cudaGetSymbolAddress((void**)&p_Q,    g_Qb);
    cudaGetSymbolAddress((void**)&p_K,    g_Kb);
    cudaGetSymbolAddress((void**)&p_V,    g_Vb);
    cudaGetSymbolAddress((void**)&p_Vt,   g_Vt);
    cudaGetSymbolAddress((void**)&p_AO,   g_AO);
    cudaGetSymbolAddress((void**)&p_WTkv, g_WTkv);
    cudaGetSymbolAddress((void**)&p_WTq,  g_WTq);
    cudaGetSymbolAddress((void**)&p_WTo,  g_WTo);

    cudaFuncSetAttribute(gemm_tc<0>, cudaFuncAttributeMaxDynamicSharedMemorySize, G_SMEM_BYTES);
    cudaFuncSetAttribute(gemm_tc<1>, cudaFuncAttributeMaxDynamicSharedMemorySize, G_SMEM_BYTES);
    cudaFuncSetAttribute(gemm_tc<2>, cudaFuncAttributeMaxDynamicSharedMemorySize, G_SMEM_BYTES);
    cudaFuncSetAttribute(attn_tc,    cudaFuncAttributeMaxDynamicSharedMemorySize, A_SMEM_BYTES);

    dim3 tb(32, 8);
    // LN row statistics
    rowstats_kernel<<<MKV / 8, 256>>>(inpkv,  p_mukv, p_rskv, CH_IN);
    rowstats_kernel<<<MQ  / 8, 256>>>(latent, p_muq,  p_rsq,  CH_LAT);
    // Weight transposes: WT[n][k] = W[k][n]
    transpose_kernel<<<dim3(32, 24, 1), tb>>>(W_K, p_WTkv,              768, 1024);
    transpose_kernel<<<dim3(32, 24, 1), tb>>>(W_V, p_WTkv + 1024 * 768, 768, 1024);
    transpose_kernel<<<dim3(32, 32, 1), tb>>>(W_Q, p_WTq, 1024, 1024);
    transpose_kernel<<<dim3(32, 32, 1), tb>>>(W_O, p_WTo, 1024, 1024);
    // Q projection (LN fused, QSCALE folded)
    gemm_tc<1><<<dim3(8, MQ / 128), 256, G_SMEM_BYTES>>>(
        latent, p_WTq, p_muq, p_rsq, ln_lat_g, ln_lat_b, nullptr, CH_LAT);
    // K|V projection (LN fused, one pass over input_kv)
    gemm_tc<0><<<dim3(16, MKV / 128), 256, G_SMEM_BYTES>>>(
        inpkv, p_WTkv, p_mukv, p_rskv, ln_in_g, ln_in_b, nullptr, CH_IN);
    // V transpose: g_Vt[bh][d][l]
    transpose_kernel<<<dim3(4, LKV / 32, BH), tb>>>(p_V, p_Vt, LKV, DH);
    // flash attention
    attn_tc<<<dim3(4, BH), 256, A_SMEM_BYTES>>>(p_Q, p_K, p_Vt, p_AO);
    // output projection
    gemm_tc<2><<<dim3(8, MQ / 128), 256, G_SMEM_BYTES>>>(
        p_AO, p_WTo, nullptr, nullptr, nullptr, nullptr, out, 1024);
}

// round 7
// speedup vs baseline: 3.8164x; 1.3076x over previous
#include <cuda_runtime.h>
#include <math.h>
#include <stdint.h>

// ---------------------------------------------------------------------------
// Problem dims
// ---------------------------------------------------------------------------
#define NB      8
#define LQ      512
#define LKV     16384
#define CH_LAT  1024
#define CH_IN   768
#define DH      128
#define NH      8
#define BH      (NB*NH)        // 64
#define MKV     (NB*LKV)       // 131072
#define MQ      (NB*LQ)        // 4096

// 1/sqrt(128) * log2(e)  (folded into Q; softmax uses exp2)
#define QSCALE  (0.08838834764831845f * 1.4426950408889634f)

// ---------------------------------------------------------------------------
// Scratch (device globals -- no allocations allowed)
// ---------------------------------------------------------------------------
__device__ float g_mu_kv[MKV], g_rs_kv[MKV];
__device__ float g_mu_q[MQ],   g_rs_q[MQ];
__device__ float g_Xkv[(size_t)MKV*CH_IN];   // tf32-rounded copy of input_kv
__device__ float g_Xq [(size_t)MQ*CH_LAT];   // tf32-rounded copy of latent
__device__ float g_Qb[(size_t)BH*LQ*DH];     // [bh][q][d], rounded, QSCALE folded
__device__ float g_Kb[(size_t)BH*LKV*DH];    // [bh][l][d], rounded
__device__ float g_Vt[(size_t)BH*DH*LKV];    // [bh][d][l], rounded (written directly)
__device__ float g_AO[(size_t)MQ*1024];      // [b*512+q][h*128+d], rounded
__device__ float g_WTkv[2048*768];           // (gamma*W)^T rounded; rows<1024: K, >=1024: V
__device__ float g_WTq[1024*1024];
__device__ float g_WTo[1024*1024];
__device__ float g_vb[2048], g_vg[2048];     // beta^T W, gamma^T W  (KV)
__device__ float g_vbq[1024], g_vgq[1024];   // (Q)

// ---------------------------------------------------------------------------
// helpers
// ---------------------------------------------------------------------------
__device__ __forceinline__ unsigned f2tf(float x) {
    unsigned r; asm("cvt.rna.tf32.f32 %0, %1;" : "=r"(r) : "f"(x)); return r;
}
__device__ __forceinline__ float ex2(float x) {
    float y; asm("ex2.approx.ftz.f32 %0, %1;" : "=f"(y) : "f"(x)); return y;
}
__device__ __forceinline__ uint32_t smem_u32(const void* p) {
    uint32_t a;
    asm("{ .reg .u64 t; cvta.to.shared.u64 t, %1; cvt.u32.u64 %0, t; }" : "=r"(a) : "l"(p));
    return a;
}
__device__ __forceinline__ void cpa16(uint32_t dst, const void* src) {
    asm volatile("cp.async.cg.shared.global [%0], [%1], 16;" :: "r"(dst), "l"(src));
}
#define CP_COMMIT() asm volatile("cp.async.commit_group;")
#define CP_WAIT(N)  asm volatile("cp.async.wait_group %0;" :: "n"(N))

__device__ __forceinline__ void mma_tf32(float* c, const unsigned* a, const unsigned* b) {
    asm volatile(
        "mma.sync.aligned.m16n8k8.row.col.f32.tf32.tf32.f32 "
        "{%0,%1,%2,%3}, {%4,%5,%6,%7}, {%8,%9}, {%0,%1,%2,%3};\n"
        : "+f"(c[0]), "+f"(c[1]), "+f"(c[2]), "+f"(c[3])
        : "r"(a[0]), "r"(a[1]), "r"(a[2]), "r"(a[3]), "r"(b[0]), "r"(b[1]));
}

// XOR swizzles (word offsets). Conflict-free for 16B staging writes and the
// per-register fragment LDS.32 reads.
__device__ __forceinline__ int sw32(int row, int k) {
    return row * 32 + ((((k >> 2) ^ row) & 7) << 2) + (k & 3);
}
__device__ __forceinline__ int sw128r(int row, int k) {
    return row * 128 + ((((k >> 2) ^ row) & 31) << 2) + (k & 3);
}
__device__ __forceinline__ int sw64v(int row, int k) {
    return row * 64 + ((((k >> 2) ^ row) & 15) << 2) + (k & 3);
}
__device__ __forceinline__ int sw64p(int row, int k) {
    return row * 64 + (((((((k >> 2) ^ row) & 15)) << 2) + (k & 3) + ((row & 1) << 4)) & 63);
}

// ---------------------------------------------------------------------------
// Row stats + tf32-rounded copy (one warp per row)
// ---------------------------------------------------------------------------
__global__ void rowstats_kernel(const float* __restrict__ X, float* __restrict__ Xr,
                                float* __restrict__ mu, float* __restrict__ rs, int cols)
{
    int row  = blockIdx.x * 8 + (threadIdx.x >> 5);
    int lane = threadIdx.x & 31;
    const float* xr = X + (size_t)row * cols;
    float* xo = Xr + (size_t)row * cols;
    float s = 0.f, s2 = 0.f;
    for (int c = lane; c < cols; c += 32) {
        float v = xr[c];
        xo[c] = __uint_as_float(f2tf(v));
        s += v; s2 += v * v;
    }
#pragma unroll
    for (int o = 16; o; o >>= 1) {
        s  += __shfl_xor_sync(0xffffffffu, s,  o);
        s2 += __shfl_xor_sync(0xffffffffu, s2, o);
    }
    if (lane == 0) {
        float m = s / cols;
        float var = fmaxf(s2 / cols - m * m, 0.f);
        mu[row] = m; rs[row] = rsqrtf(var + 1e-5f);
    }
}

// ---------------------------------------------------------------------------
// Weight transpose: out[c][r] = round(in[r][c] * (scale?scale[r]:1))
// ---------------------------------------------------------------------------
__global__ void wtrans_kernel(const float* __restrict__ in, float* __restrict__ out,
                              int R, int C, const float* __restrict__ scale)
{
    __shared__ float t[32][33];
    int c0 = blockIdx.x * 32, r0 = blockIdx.y * 32;
    int tx = threadIdx.x, ty = threadIdx.y;
#pragma unroll
    for (int j = 0; j < 4; j++) {
        int r = r0 + ty + j * 8;
        float v = in[(size_t)r * C + c0 + tx];
        if (scale) v *= scale[r];
        t[ty + j * 8][tx] = __uint_as_float(f2tf(v));
    }
    __syncthreads();
#pragma unroll
    for (int j = 0; j < 4; j++)
        out[(size_t)(c0 + ty + j * 8) * R + r0 + tx] = t[tx][ty + j * 8];
}

// ---------------------------------------------------------------------------
// vb[n] = sum_k beta[k] W[k][n];  vg[n] = sum_k gamma[k] W[k][n]
// ---------------------------------------------------------------------------
__global__ void vbvg_kernel(const float* __restrict__ W, const float* __restrict__ gamma,
                            const float* __restrict__ beta, float* __restrict__ vb,
                            float* __restrict__ vg, int K, int N)
{
    int n = blockIdx.x * 256 + threadIdx.x;
    float sb = 0.f, sg = 0.f;
    for (int k = 0; k < K; k++) {
        float w = W[(size_t)k * N + n];
        sb += beta[k] * w;
        sg += gamma[k] * w;
    }
    vb[n] = sb; vg[n] = sg;
}

// ---------------------------------------------------------------------------
// TF32 GEMM: block 128x256, BK=32, 256 threads (8 warps 2x4), warp tile 64x64.
// cp.async 4-stage pipeline. A raw (rounded), B = pre-scaled rounded W^T.
// LN folded into epilogue: C = rs*acc + vb - mu*rs*vg.
// MODE 0: -> g_Kb (n<1024) / g_Vt transposed (n>=1024)
// MODE 1: -> g_Qb rounded, *QSCALE
// MODE 2: -> row-major C (final output)
// ---------------------------------------------------------------------------
#define G_STAGE 49152                 // A 16KB + B 32KB
#define G_SMEM  (4*G_STAGE)           // 192KB

template<int MODE>
__global__ __launch_bounds__(256, 1)
void gemm_tc(const float* __restrict__ A, const float* __restrict__ WT,
             const float* __restrict__ mu, const float* __restrict__ rs,
             const float* __restrict__ vb, const float* __restrict__ vg,
             float* __restrict__ C, int K)
{
    extern __shared__ char sm[];
    const uint32_t sb = smem_u32(sm);
    const int tid = threadIdx.x;
    const int lane = tid & 31, wid = tid >> 5;
    const int wm = wid >> 2, wn = wid & 3;
    const int g = lane >> 2, t = lane & 3;
    const int m0 = blockIdx.y * 128, n0 = blockIdx.x * 256;
    const int KC = K >> 5;

    const float* Ag = A  + (size_t)m0 * K;
    const float* Bg = WT + (size_t)n0 * K;

    // staging assignments
    const float* a_src[4]; uint32_t a_dst[4];
#pragma unroll
    for (int it = 0; it < 4; it++) {
        int idx = tid + it * 256, row = idx >> 3, f4 = idx & 7;
        a_src[it] = Ag + (size_t)row * K + f4 * 4;
        a_dst[it] = sw32(row, f4 * 4) * 4;
    }
    const float* b_src[8]; uint32_t b_dst[8];
#pragma unroll
    for (int it = 0; it < 8; it++) {
        int idx = tid + it * 256, row = idx >> 3, f4 = idx & 7;
        b_src[it] = Bg + (size_t)row * K + f4 * 4;
        b_dst[it] = 16384 + sw32(row, f4 * 4) * 4;
    }

    float acc[4][8][4];
#pragma unroll
    for (int i = 0; i < 4; i++)
#pragma unroll
        for (int j = 0; j < 8; j++)
#pragma unroll
            for (int r = 0; r < 4; r++) acc[i][j][r] = 0.f;

    // prologue: stages 0..2
#pragma unroll
    for (int s = 0; s < 3; s++) {
        uint32_t base = sb + s * G_STAGE;
        int k0 = s * 32;
#pragma unroll
        for (int it = 0; it < 4; it++) cpa16(base + a_dst[it], a_src[it] + k0);
#pragma unroll
        for (int it = 0; it < 8; it++) cpa16(base + b_dst[it], b_src[it] + k0);
        CP_COMMIT();
    }

    for (int c = 0; c < KC; c++) {
        CP_WAIT(2);
        __syncthreads();
        if (c + 3 < KC) {
            uint32_t base = sb + ((c + 3) & 3) * G_STAGE;
            int k0 = (c + 3) * 32;
#pragma unroll
            for (int it = 0; it < 4; it++) cpa16(base + a_dst[it], a_src[it] + k0);
#pragma unroll
            for (int it = 0; it < 8; it++) cpa16(base + b_dst[it], b_src[it] + k0);
        }
        CP_COMMIT();

        const unsigned* ab = (const unsigned*)(sm + (c & 3) * G_STAGE);
        const unsigned* bb = ab + 4096;
#pragma unroll
        for (int ks = 0; ks < 4; ks++) {
            int kk = ks * 8 + t;
            unsigned afr[4][4], bfr[8][2];
#pragma unroll
            for (int i = 0; i < 4; i++) {
                int m = wm * 64 + i * 16 + g;
                afr[i][0] = ab[sw32(m,     kk)];
                afr[i][1] = ab[sw32(m + 8, kk)];
                afr[i][2] = ab[sw32(m,     kk + 4)];
                afr[i][3] = ab[sw32(m + 8, kk + 4)];
            }
#pragma unroll
            for (int j = 0; j < 8; j++) {
                int n = wn * 64 + j * 8 + g;
                bfr[j][0] = bb[sw32(n, kk)];
                bfr[j][1] = bb[sw32(n, kk + 4)];
            }
#pragma unroll
            for (int i = 0; i < 4; i++)
#pragma unroll
                for (int j = 0; j < 8; j++)
                    mma_tf32(acc[i][j], afr[i], bfr[j]);
        }
    }
    CP_WAIT(0);
    __syncthreads();   // all compute done; stage smem reusable

    // ---- epilogue: LN correction then per-mode store
    float Rr[8], MR[8];
    if (MODE != 2) {
#pragma unroll
        for (int i = 0; i < 4; i++)
#pragma unroll
            for (int half = 0; half < 2; half++) {
                int r = m0 + wm * 64 + i * 16 + g + half * 8;
                float rv = rs[r];
                Rr[i * 2 + half] = rv;
                MR[i * 2 + half] = mu[r] * rv;
            }
    }
    float vbv[16], vgv[16];
    if (MODE != 2) {
#pragma unroll
        for (int j = 0; j < 8; j++) {
            int cg = n0 + wn * 64 + j * 8 + 2 * t;
            vbv[2*j] = vb[cg]; vbv[2*j+1] = vb[cg+1];
            vgv[2*j] = vg[cg]; vgv[2*j+1] = vg[cg+1];
        }
    }

    const bool vpart = (MODE == 0) && (n0 >= 1024);
    float* st = (float*)sm;   // 256x132 transpose buffer (V part)

#pragma unroll
    for (int i = 0; i < 4; i++) {
#pragma unroll
        for (int j = 0; j < 8; j++) {
#pragma unroll
            for (int half = 0; half < 2; half++) {
                int rl = wm * 64 + i * 16 + g + half * 8;
                int r = m0 + rl;
                int cl = wn * 64 + j * 8 + 2 * t;
                int cg = n0 + cl;
                float v0 = acc[i][j][half * 2 + 0];
                float v1 = acc[i][j][half * 2 + 1];
                if (MODE != 2) {
                    float R = Rr[i * 2 + half], M = MR[i * 2 + half];
                    v0 = R * v0 + vbv[2*j]   - M * vgv[2*j];
                    v1 = R * v1 + vbv[2*j+1] - M * vgv[2*j+1];
                }
                if (MODE == 0) {
                    if (!vpart) {
                        int h = cg >> 7, d = cg & 127;
                        int bb2 = r >> 14, l = r & 16383;
                        float* dst = g_Kb + ((((size_t)(bb2 * 8 + h)) << 14) + l) * 128 + d;
                        dst[0] = __uint_as_float(f2tf(v0));
                        dst[1] = __uint_as_float(f2tf(v1));
                    } else {
                        st[(cl)     * 132 + rl] = __uint_as_float(f2tf(v0));
                        st[(cl + 1) * 132 + rl] = __uint_as_float(f2tf(v1));
                    }
                } else if (MODE == 1) {
                    int h = cg >> 7, d = cg & 127;
                    int bb2 = r >> 9, q = r & 511;
                    float* dst = g_Qb + (((size_t)(bb2 * 8 + h)) * 512 + q) * 128 + d;
                    dst[0] = __uint_as_float(f2tf(QSCALE * v0));
                    dst[1] = __uint_as_float(f2tf(QSCALE * v1));
                } else {
                    *(float2*)(C + (size_t)r * 1024 + cg) = make_float2(v0, v1);
                }
            }
        }
    }
    if (vpart) {
        __syncthreads();
        int bb2 = m0 >> 14, l0 = m0 & 16383;
        for (int cl = 0; cl < 32; cl++) {
            int c = wid * 32 + cl;
            int cg = n0 + c - 1024;
            int h = cg >> 7, d = cg & 127;
            float4 v = *(const float4*)&st[c * 132 + lane * 4];
            *(float4*)(g_Vt + ((size_t)(bb2 * 8 + h) * 128 + d) * LKV + l0 + lane * 4) = v;
        }
    }
}

// ---------------------------------------------------------------------------
// Flash attention (max-free, exp2). Br=128, Bc=64, 256 threads.
// cp.async 2-stage K/V prefetch. Chunk ci: K offset = ci*64*128, V offset = ci*64.
//   S:  warps 4x2, warp 32x32;  PV: warps 2x4, warp 64x32.
// Smem: Q 64KB | stage0 K32+V32 | stage1 K32+V32 | P 32KB (ls overlays P).
// ---------------------------------------------------------------------------
#define AT_Q     0
#define AT_STG   65536
#define AT_P     196608
#define A_SMEM_BYTES 229376

__global__ __launch_bounds__(256, 1)
void attn_tc(const float* __restrict__ Qb, const float* __restrict__ Kb,
             const float* __restrict__ Vt, float* __restrict__ AO)
{
    extern __shared__ char sm[];
    const uint32_t sb = smem_u32(sm);
    const int tid = threadIdx.x;
    const int lane = tid & 31, wid = tid >> 5;
    const int g = lane >> 2, t = lane & 3;
    const int bh = blockIdx.y;
    const int q0 = blockIdx.x * 128;

    const int wq4 = wid & 3, wl = wid >> 2;   // S phase
    const int wq2 = wid & 1, wd = wid >> 1;   // PV phase

    const float* Qg = Qb + ((size_t)bh * LQ + q0) * DH;
    const float* Kg = Kb + (size_t)bh * LKV * DH;
    const float* Vg = Vt + (size_t)bh * DH * LKV;

    const unsigned* Qs = (const unsigned*)(sm + AT_Q);
    unsigned* Ps = (unsigned*)(sm + AT_P);

    // staging assignments
    const float* k_src[8]; uint32_t k_dst[8];
#pragma unroll
    for (int it = 0; it < 8; it++) {
        int idx = tid + it * 256, row = idx >> 5, f4 = idx & 31;
        k_src[it] = Kg + (size_t)row * 128 + f4 * 4;
        k_dst[it] = sw128r(row, f4 * 4) * 4;
    }
    const float* v_src[8]; uint32_t v_dst[8];
#pragma unroll
    for (int it = 0; it < 8; it++) {
        int idx = tid + it * 256, d = idx >> 4, f4 = idx & 15;
        v_src[it] = Vg + (size_t)d * LKV + f4 * 4;
        v_dst[it] = 32768 + sw64v(d, f4 * 4) * 4;
    }

    // prologue: Q + chunk0 in group 0; chunk1 in group 1
#pragma unroll
    for (int it = 0; it < 16; it++) {
        int idx = tid + it * 256, row = idx >> 5, f4 = idx & 31;
        cpa16(sb + AT_Q + sw128r(row, f4 * 4) * 4, Qg + (size_t)row * 128 + f4 * 4);
    }
    {   // chunk 0: K offset 0, V offset 0
        uint32_t base = sb + AT_STG;
#pragma unroll
        for (int it = 0; it < 8; it++) cpa16(base + k_dst[it], k_src[it]);
#pragma unroll
        for (int it = 0; it < 8; it++) cpa16(base + v_dst[it], v_src[it]);
        CP_COMMIT();
    }
    {   // chunk 1: K offset 64*128, V offset 64
        uint32_t base = sb + AT_STG + 65536;
#pragma unroll
        for (int it = 0; it < 8; it++) cpa16(base + k_dst[it], k_src[it] + (size_t)64 * 128);
#pragma unroll
        for (int it = 0; it < 8; it++) cpa16(base + v_dst[it], v_src[it] + 64);
        CP_COMMIT();
    }

    float oacc[4][4][4];
#pragma unroll
    for (int i = 0; i < 4; i++)
#pragma unroll
        for (int j = 0; j < 4; j++)
#pragma unroll
            for (int r = 0; r < 4; r++) oacc[i][j][r] = 0.f;
    float rsum[2][2] = {{0.f, 0.f}, {0.f, 0.f}};

    const int NC = LKV / 64;
    for (int ci = 0; ci < NC; ci++) {
        CP_WAIT(1);
        __syncthreads();
        const unsigned* Kc = (const unsigned*)(sm + AT_STG + (ci & 1) * 65536);
        const unsigned* Vc = Kc + 8192;

        // ---- S = Q K^T
        float sac[2][4][4];
#pragma unroll
        for (int i = 0; i < 2; i++)
#pragma unroll
            for (int j = 0; j < 4; j++)
#pragma unroll
                for (int r = 0; r < 4; r++) sac[i][j][r] = 0.f;
#pragma unroll
        for (int ks = 0; ks < 16; ks++) {
            int kk = ks * 8 + t;
            unsigned afr[2][4], bfr[4][2];
#pragma unroll
            for (int i = 0; i < 2; i++) {
                int m = wq4 * 32 + i * 16 + g;
                afr[i][0] = Qs[sw128r(m,     kk)];
                afr[i][1] = Qs[sw128r(m + 8, kk)];
                afr[i][2] = Qs[sw128r(m,     kk + 4)];
                afr[i][3] = Qs[sw128r(m + 8, kk + 4)];
            }
#pragma unroll
            for (int j = 0; j < 4; j++) {
                int n = wl * 32 + j * 8 + g;
                bfr[j][0] = Kc[sw128r(n, kk)];
                bfr[j][1] = Kc[sw128r(n, kk + 4)];
            }
#pragma unroll
            for (int i = 0; i < 2; i++)
#pragma unroll
                for (int j = 0; j < 4; j++)
                    mma_tf32(sac[i][j], afr[i], bfr[j]);
        }

        // ---- P = exp2(S), row sums, store P
#pragma unroll
        for (int i = 0; i < 2; i++) {
            int r0 = wq4 * 32 + i * 16 + g;
#pragma unroll
            for (int j = 0; j < 4; j++) {
                int cc = wl * 32 + j * 8 + 2 * t;
                float p0 = ex2(sac[i][j][0]);
                float p1 = ex2(sac[i][j][1]);
                float p2 = ex2(sac[i][j][2]);
                float p3 = ex2(sac[i][j][3]);
                rsum[i][0] += p0 + p1;
                rsum[i][1] += p2 + p3;
                uint2 u0; u0.x = f2tf(p0); u0.y = f2tf(p1);
                uint2 u1; u1.x = f2tf(p2); u1.y = f2tf(p3);
                *(uint2*)&Ps[sw64p(r0,     cc)] = u0;
                *(uint2*)&Ps[sw64p(r0 + 8, cc)] = u1;
            }
        }
        __syncthreads();

        // ---- O += P V
#pragma unroll
        for (int ks = 0; ks < 8; ks++) {
            int kk = ks * 8 + t;
            unsigned afr[4][4], bfr[4][2];
#pragma unroll
            for (int i = 0; i < 4; i++) {
                int m = wq2 * 64 + i * 16 + g;
                afr[i][0] = Ps[sw64p(m,     kk)];
                afr[i][1] = Ps[sw64p(m + 8, kk)];
                afr[i][2] = Ps[sw64p(m,     kk + 4)];
                afr[i][3] = Ps[sw64p(m + 8, kk + 4)];
            }
#pragma unroll
            for (int j = 0; j < 4; j++) {
                int n = wd * 32 + j * 8 + g;
                bfr[j][0] = Vc[sw64v(n, kk)];
                bfr[j][1] = Vc[sw64v(n, kk + 4)];
            }
#pragma unroll
            for (int i = 0; i < 4; i++)
#pragma unroll
                for (int j = 0; j < 4; j++)
                    mma_tf32(oacc[i][j], afr[i], bfr[j]);
        }
        __syncthreads();

        if (ci + 2 < NC) {
            uint32_t base = sb + AT_STG + (ci & 1) * 65536;
            size_t koff = (size_t)(ci + 2) * 64 * 128;
            int voff = (ci + 2) * 64;
#pragma unroll
            for (int it = 0; it < 8; it++) cpa16(base + k_dst[it], k_src[it] + koff);
#pragma unroll
            for (int it = 0; it < 8; it++) cpa16(base + v_dst[it], v_src[it] + voff);
        }
        CP_COMMIT();
    }

    // ---- row-sum reduction (ls overlays P region -- all P reads done)
    float* ls = (float*)Ps;
#pragma unroll
    for (int i = 0; i < 2; i++)
#pragma unroll
        for (int h = 0; h < 2; h++) {
            float v = rsum[i][h];
            v += __shfl_xor_sync(0xffffffffu, v, 1);
            v += __shfl_xor_sync(0xffffffffu, v, 2);
            rsum[i][h] = v;
        }
    if (t == 0) {
#pragma unroll
        for (int i = 0; i < 2; i++) {
            int r = wq4 * 32 + i * 16 + g;
            ls[wl * 128 + r]     = rsum[i][0];
            ls[wl * 128 + r + 8] = rsum[i][1];
        }
    }
    __syncthreads();

    // ---- epilogue: normalize, round, scatter
    int bb2 = bh >> 3, h = bh & 7;
#pragma unroll
    for (int i = 0; i < 4; i++) {
#pragma unroll
        for (int half = 0; half < 2; half++) {
            int r = wq2 * 64 + i * 16 + g + half * 8;
            float inv = 1.f / (ls[r] + ls[128 + r]);
            size_t rowoff = ((size_t)(bb2 * 512 + q0 + r)) * 1024 + h * 128;
#pragma unroll
            for (int j = 0; j < 4; j++) {
                int cc = wd * 32 + j * 8 + 2 * t;
                float* dst = AO + rowoff + cc;
                dst[0] = __uint_as_float(f2tf(oacc[i][j][half * 2]     * inv));
                dst[1] = __uint_as_float(f2tf(oacc[i][j][half * 2 + 1] * inv));
            }
        }
    }
}

// ---------------------------------------------------------------------------
// Launcher (graph-capturable)
// ---------------------------------------------------------------------------
extern "C" void kernel_launch(void* const* d_in, const int* in_sizes, int n_in,
                              void* d_out, int out_size)
{
    (void)in_sizes; (void)n_in; (void)out_size;
    const float* latent   = (const float*)d_in[0];
    const float* inpkv    = (const float*)d_in[1];
    const float* W_Q      = (const float*)d_in[2];
    const float* W_K      = (const float*)d_in[3];
    const float* W_V      = (const float*)d_in[4];
    const float* W_O      = (const float*)d_in[5];
    const float* ln_lat_g = (const float*)d_in[6];
    const float* ln_lat_b = (const float*)d_in[7];
    const float* ln_in_g  = (const float*)d_in[8];
    const float* ln_in_b  = (const float*)d_in[9];
    float* out = (float*)d_out;

    float *p_mukv, *p_rskv, *p_muq, *p_rsq, *p_Q, *p_K, *p_Vt, *p_AO;
    float *p_WTkv, *p_WTq, *p_WTo, *p_Xkv, *p_Xq, *p_vb, *p_vg, *p_vbq, *p_vgq;
    cudaGetSymbolAddress((void**)&p_mukv, g_mu_kv);
    cudaGetSymbolAddress((void**)&p_rskv, g_rs_kv);
    cudaGetSymbolAddress((void**)&p_muq,  g_mu_q);
    cudaGetSymbolAddress((void**)&p_rsq,  g_rs_q);
    cudaGetSymbolAddress((void**)&p_Q,    g_Qb);
    cudaGetSymbolAddress((void**)&p_K,    g_Kb);
    cudaGetSymbolAddress((void**)&p_Vt,   g_Vt);
    cudaGetSymbolAddress((void**)&p_AO,   g_AO);
    cudaGetSymbolAddress((void**)&p_WTkv, g_WTkv);
    cudaGetSymbolAddress((void**)&p_WTq,  g_WTq);
    cudaGetSymbolAddress((void**)&p_WTo,  g_WTo);
    cudaGetSymbolAddress((void**)&p_Xkv,  g_Xkv);
    cudaGetSymbolAddress((void**)&p_Xq,   g_Xq);
    cudaGetSymbolAddress((void**)&p_vb,   g_vb);
    cudaGetSymbolAddress((void**)&p_vg,   g_vg);
    cudaGetSymbolAddress((void**)&p_vbq,  g_vbq);
    cudaGetSymbolAddress((void**)&p_vgq,  g_vgq);

    cudaFuncSetAttribute(gemm_tc<0>, cudaFuncAttributeMaxDynamicSharedMemorySize, G_SMEM);
    cudaFuncSetAttribute(gemm_tc<1>, cudaFuncAttributeMaxDynamicSharedMemorySize, G_SMEM);
    cudaFuncSetAttribute(gemm_tc<2>, cudaFuncAttributeMaxDynamicSharedMemorySize, G_SMEM);
    cudaFuncSetAttribute(attn_tc,    cudaFuncAttributeMaxDynamicSharedMemorySize, A_SMEM_BYTES);

    dim3 tb(32, 8);
    // LN row stats + rounded copies
    rowstats_kernel<<<MKV / 8, 256>>>(inpkv,  p_Xkv, p_mukv, p_rskv, CH_IN);
    rowstats_kernel<<<MQ  / 8, 256>>>(latent, p_Xq,  p_muq,  p_rsq,  CH_LAT);
    // Weight transposes (gamma folded, rounded)
    wtrans_kernel<<<dim3(32, 24), tb>>>(W_K, p_WTkv,              768, 1024, ln_in_g);
    wtrans_kernel<<<dim3(32, 24), tb>>>(W_V, p_WTkv + 1024 * 768, 768, 1024, ln_in_g);
    wtrans_kernel<<<dim3(32, 32), tb>>>(W_Q, p_WTq, 1024, 1024, ln_lat_g);
    wtrans_kernel<<<dim3(32, 32), tb>>>(W_O, p_WTo, 1024, 1024, nullptr);
    // LN fold vectors
    vbvg_kernel<<<4, 256>>>(W_K, ln_in_g,  ln_in_b,  p_vb,        p_vg,        768, 1024);
    vbvg_kernel<<<4, 256>>>(W_V, ln_in_g,  ln_in_b,  p_vb + 1024, p_vg + 1024, 768, 1024);
    vbvg_kernel<<<4, 256>>>(W_Q, ln_lat_g, ln_lat_b, p_vbq,       p_vgq,       1024, 1024);
    // Q projection
    gemm_tc<1><<<dim3(4, 32), 256, G_SMEM>>>(p_Xq, p_WTq, p_muq, p_rsq,
                                             p_vbq, p_vgq, nullptr, CH_LAT);
    // K|V projection (V written transposed)
    gemm_tc<0><<<dim3(8, 1024), 256, G_SMEM>>>(p_Xkv, p_WTkv, p_mukv, p_rskv,
                                               p_vb, p_vg, nullptr, CH_IN);
    // attention
    attn_tc<<<dim3(4, BH), 256, A_SMEM_BYTES>>>(p_Q, p_K, p_Vt, p_AO);
    // output projection
    gemm_tc<2><<<dim3(4, 32), 256, G_SMEM>>>(p_AO, p_WTo, nullptr, nullptr,
                                             nullptr, nullptr, out, 1024);
}

// round 8
// speedup vs baseline: 7.1556x; 1.8749x over previous
#include <cuda_runtime.h>
#include <cuda_fp16.h>
#include <math.h>
#include <stdint.h>

// ---------------------------------------------------------------------------
// Problem dims
// ---------------------------------------------------------------------------
#define NB      8
#define LQ      512
#define LKV     16384
#define CH_LAT  1024
#define CH_IN   768
#define DH      128
#define NH      8
#define BH      (NB*NH)        // 64
#define MKV     (NB*LKV)       // 131072
#define MQ      (NB*LQ)        // 4096

// 1/sqrt(128) * log2(e)  (folded into Q; softmax uses exp2)
#define QSCALE  (0.08838834764831845f * 1.4426950408889634f)

// ---------------------------------------------------------------------------
// Scratch (device globals; uint4-typed for 16B alignment, cast to __half)
// ---------------------------------------------------------------------------
__device__ float g_mu_kv[MKV], g_rs_kv[MKV];
__device__ float g_mu_q[MQ],   g_rs_q[MQ];
__device__ uint4 g_Xkv4[(size_t)MKV*CH_IN/8];    // half copy of input_kv
__device__ uint4 g_Xq4 [(size_t)MQ*CH_LAT/8];    // half copy of latent
__device__ uint4 g_Qb4 [(size_t)BH*LQ*DH/8];     // half [bh][q][d], QSCALE folded
__device__ uint4 g_Kb4 [(size_t)BH*LKV*DH/8];    // half [bh][l][d]
__device__ uint4 g_Vt4 [(size_t)BH*DH*LKV/8];    // half [bh][d][l]
__device__ uint4 g_AO4 [(size_t)MQ*1024/8];      // half [b*512+q][h*128+d]
__device__ uint4 g_WTkv4[2048*768/8];            // half (gamma*W)^T; <1024: K, >=1024: V
__device__ uint4 g_WTq4 [1024*1024/8];
__device__ uint4 g_WTo4 [1024*1024/8];
__device__ float g_vb[2048], g_vg[2048];         // beta^T W, gamma^T W (KV)
__device__ float g_vbq[1024], g_vgq[1024];       // (Q)

// ---------------------------------------------------------------------------
// helpers
// ---------------------------------------------------------------------------
__device__ __forceinline__ float ex2(float x) {
    float y; asm("ex2.approx.ftz.f32 %0, %1;" : "=f"(y) : "f"(x)); return y;
}
__device__ __forceinline__ unsigned pack2h(float a, float b) {
    __half2 h = __floats2half2_rn(a, b);
    return *(unsigned*)&h;
}
__device__ __forceinline__ uint32_t smem_u32(const void* p) {
    uint32_t a;
    asm("{ .reg .u64 t; cvta.to.shared.u64 t, %1; cvt.u32.u64 %0, t; }" : "=r"(a) : "l"(p));
    return a;
}
__device__ __forceinline__ void cpa16(uint32_t dst, const void* src) {
    asm volatile("cp.async.cg.shared.global [%0], [%1], 16;" :: "r"(dst), "l"(src));
}
#define CP_COMMIT() asm volatile("cp.async.commit_group;")
#define CP_WAIT(N)  asm volatile("cp.async.wait_group %0;" :: "n"(N))

__device__ __forceinline__ void mma_f16(float* c, const unsigned* a, const unsigned* b) {
    asm volatile(
        "mma.sync.aligned.m16n8k16.row.col.f32.f16.f16.f32 "
        "{%0,%1,%2,%3}, {%4,%5,%6,%7}, {%8,%9}, {%0,%1,%2,%3};\n"
        : "+f"(c[0]), "+f"(c[1]), "+f"(c[2]), "+f"(c[3])
        : "r"(a[0]), "r"(a[1]), "r"(a[2]), "r"(a[3]), "r"(b[0]), "r"(b[1]));
}

// Swizzled word (b32 = half2) offsets. Conflict-free for 16B staging writes
// and the per-register fragment LDS.32 reads (verified per pattern).
__device__ __forceinline__ int swA16(int row, int w) {   // 16-word (32-half) rows
    return row * 16 + (((((w >> 2) ^ (row >> 1)) & 3)) << 2) + (w & 3);
}
__device__ __forceinline__ int swQ64(int row, int w) {   // 64-word (128-half) rows
    return row * 64 + ((((w >> 2) ^ row) & 15) << 2) + (w & 3);
}
__device__ __forceinline__ int swV32(int row, int w) {   // 32-word (64-half) rows
    return row * 32 + ((((w >> 2) ^ row) & 7) << 2) + (w & 3);
}

// ---------------------------------------------------------------------------
// Row stats + half-rounded copy (one warp per row)
// ---------------------------------------------------------------------------
__global__ void rowstats_kernel(const float* __restrict__ X, __half* __restrict__ Xh,
                                float* __restrict__ mu, float* __restrict__ rs, int cols)
{
    int row  = blockIdx.x * 8 + (threadIdx.x >> 5);
    int lane = threadIdx.x & 31;
    const float* xr = X + (size_t)row * cols;
    __half* xo = Xh + (size_t)row * cols;
    float s = 0.f, s2 = 0.f;
    for (int c = lane; c < cols; c += 32) {
        float v = xr[c];
        xo[c] = __float2half_rn(v);
        s += v; s2 += v * v;
    }
#pragma unroll
    for (int o = 16; o; o >>= 1) {
        s  += __shfl_xor_sync(0xffffffffu, s,  o);
        s2 += __shfl_xor_sync(0xffffffffu, s2, o);
    }
    if (lane == 0) {
        float m = s / cols;
        float var = fmaxf(s2 / cols - m * m, 0.f);
        mu[row] = m; rs[row] = rsqrtf(var + 1e-5f);
    }
}

// ---------------------------------------------------------------------------
// Weight transpose: out[c][r] = half(in[r][c] * (scale?scale[r]:1))
// ---------------------------------------------------------------------------
__global__ void wtrans_kernel(const float* __restrict__ in, __half* __restrict__ out,
                              int R, int C, const float* __restrict__ scale)
{
    __shared__ float t[32][33];
    int c0 = blockIdx.x * 32, r0 = blockIdx.y * 32;
    int tx = threadIdx.x, ty = threadIdx.y;
#pragma unroll
    for (int j = 0; j < 4; j++) {
        int r = r0 + ty + j * 8;
        float v = in[(size_t)r * C + c0 + tx];
        if (scale) v *= scale[r];
        t[ty + j * 8][tx] = v;
    }
    __syncthreads();
#pragma unroll
    for (int j = 0; j < 4; j++)
        out[(size_t)(c0 + ty + j * 8) * R + r0 + tx] = __float2half_rn(t[tx][ty + j * 8]);
}

// ---------------------------------------------------------------------------
// vb[n] = beta^T W[:,n]; vg[n] = gamma^T W[:,n].  Two weight matrices packed:
// n < 1024 -> W0, else W1 (col n-1024).
// ---------------------------------------------------------------------------
__global__ void vbvg_kernel(const float* __restrict__ W0, const float* __restrict__ W1,
                            const float* __restrict__ gamma, const float* __restrict__ beta,
                            float* __restrict__ vb, float* __restrict__ vg, int K)
{
    int n = blockIdx.x * 256 + threadIdx.x;
    const float* W = (n < 1024) ? W0 : W1;
    int nn = n & 1023;
    float sb = 0.f, sg = 0.f;
    for (int k = 0; k < K; k++) {
        float w = W[(size_t)k * 1024 + nn];
        sb += beta[k] * w;
        sg += gamma[k] * w;
    }
    vb[n] = sb; vg[n] = sg;
}

// ---------------------------------------------------------------------------
// FP16 GEMM: block 128x256, BK=32, 256 threads (8 warps 2x4), warp 64x64,
// m16n8k16. cp.async 4-stage pipeline (stage = A 8KB + B 16KB = 24KB).
// LN folded into epilogue: C = rs*acc + vb - mu*rs*vg.
// MODE 0: -> g_Kb half (n<1024) / g_Vt half transposed (n>=1024)
// MODE 1: -> g_Qb half, *QSCALE
// MODE 2: -> float row-major C (final output)
// ---------------------------------------------------------------------------
#define G_STAGE 24576
#define G_SMEM  (4*G_STAGE)      // 96KB

template<int MODE>
__global__ __launch_bounds__(256, 1)
void gemm_h(const __half* __restrict__ A, const __half* __restrict__ WT,
            const float* __restrict__ mu, const float* __restrict__ rs,
            const float* __restrict__ vb, const float* __restrict__ vg,
            float* __restrict__ C, int K)
{
    extern __shared__ char sm[];
    const uint32_t sb = smem_u32(sm);
    const int tid = threadIdx.x;
    const int lane = tid & 31, wid = tid >> 5;
    const int wm = wid >> 2, wn = wid & 3;
    const int g = lane >> 2, t = lane & 3;
    const int m0 = blockIdx.y * 128, n0 = blockIdx.x * 256;
    const int KC = K >> 5;

    const __half* Ag = A  + (size_t)m0 * K;
    const __half* Bg = WT + (size_t)n0 * K;

    // staging: A 128 rows x 4 x16B blocks (2 its); B 256 rows x 4 (4 its)
    const __half* a_src[2]; uint32_t a_dst[2];
#pragma unroll
    for (int it = 0; it < 2; it++) {
        int idx = tid + it * 256, row = idx >> 2, blk = idx & 3;
        a_src[it] = Ag + (size_t)row * K + blk * 8;
        a_dst[it] = (row * 16 + ((((blk ^ (row >> 1)) & 3)) << 2)) * 4;
    }
    const __half* b_src[4]; uint32_t b_dst[4];
#pragma unroll
    for (int it = 0; it < 4; it++) {
        int idx = tid + it * 256, row = idx >> 2, blk = idx & 3;
        b_src[it] = Bg + (size_t)row * K + blk * 8;
        b_dst[it] = 8192 + (row * 16 + ((((blk ^ (row >> 1)) & 3)) << 2)) * 4;
    }

    float acc[4][8][4];
#pragma unroll
    for (int i = 0; i < 4; i++)
#pragma unroll
        for (int j = 0; j < 8; j++)
#pragma unroll
            for (int r = 0; r < 4; r++) acc[i][j][r] = 0.f;

    // prologue: stages 0..2
#pragma unroll
    for (int s = 0; s < 3; s++) {
        uint32_t base = sb + s * G_STAGE;
        int k0 = s * 32;
#pragma unroll
        for (int it = 0; it < 2; it++) cpa16(base + a_dst[it], a_src[it] + k0);
#pragma unroll
        for (int it = 0; it < 4; it++) cpa16(base + b_dst[it], b_src[it] + k0);
        CP_COMMIT();
    }

    for (int c = 0; c < KC; c++) {
        CP_WAIT(2);
        __syncthreads();
        if (c + 3 < KC) {
            uint32_t base = sb + ((c + 3) & 3) * G_STAGE;
            int k0 = (c + 3) * 32;
#pragma unroll
            for (int it = 0; it < 2; it++) cpa16(base + a_dst[it], a_src[it] + k0);
#pragma unroll
            for (int it = 0; it < 4; it++) cpa16(base + b_dst[it], b_src[it] + k0);
        }
        CP_COMMIT();

        const unsigned* ab = (const unsigned*)(sm + (c & 3) * G_STAGE);
        const unsigned* bb = ab + 2048;
#pragma unroll
        for (int ks = 0; ks < 2; ks++) {
            int kb = ks * 8 + t;
            unsigned afr[4][4], bfr[8][2];
#pragma unroll
            for (int i = 0; i < 4; i++) {
                int m = wm * 64 + i * 16 + g;
                afr[i][0] = ab[swA16(m,     kb)];
                afr[i][1] = ab[swA16(m + 8, kb)];
                afr[i][2] = ab[swA16(m,     kb + 4)];
                afr[i][3] = ab[swA16(m + 8, kb + 4)];
            }
#pragma unroll
            for (int j = 0; j < 8; j++) {
                int n = wn * 64 + j * 8 + g;
                bfr[j][0] = bb[swA16(n, kb)];
                bfr[j][1] = bb[swA16(n, kb + 4)];
            }
#pragma unroll
            for (int i = 0; i < 4; i++)
#pragma unroll
                for (int j = 0; j < 8; j++)
                    mma_f16(acc[i][j], afr[i], bfr[j]);
        }
    }
    CP_WAIT(0);
    __syncthreads();   // compute done; stage smem reusable

    // ---- epilogue: LN correction then per-mode store
    float Rr[8], MR[8];
    if (MODE != 2) {
#pragma unroll
        for (int i = 0; i < 4; i++)
#pragma unroll
            for (int half = 0; half < 2; half++) {
                int r = m0 + wm * 64 + i * 16 + g + half * 8;
                float rv = rs[r];
                Rr[i * 2 + half] = rv;
                MR[i * 2 + half] = mu[r] * rv;
            }
    }
    float vbv[16], vgv[16];
    if (MODE != 2) {
#pragma unroll
        for (int j = 0; j < 8; j++) {
            int cg = n0 + wn * 64 + j * 8 + 2 * t;
            vbv[2*j] = vb[cg]; vbv[2*j+1] = vb[cg+1];
            vgv[2*j] = vg[cg]; vgv[2*j+1] = vg[cg+1];
        }
    }

    const bool vpart = (MODE == 0) && (n0 >= 1024);
    __half* st = (__half*)sm;   // 256 x 136-half transpose buffer (V part)
    __half* Kb = (__half*)g_Kb4;
    __half* Qb = (__half*)g_Qb4;
    __half* Vt = (__half*)g_Vt4;

#pragma unroll
    for (int i = 0; i < 4; i++) {
#pragma unroll
        for (int j = 0; j < 8; j++) {
#pragma unroll
            for (int half = 0; half < 2; half++) {
                int rl = wm * 64 + i * 16 + g + half * 8;
                int r = m0 + rl;
                int cl = wn * 64 + j * 8 + 2 * t;
                int cg = n0 + cl;
                float v0 = acc[i][j][half * 2 + 0];
                float v1 = acc[i][j][half * 2 + 1];
                if (MODE != 2) {
                    float R = Rr[i * 2 + half], M = MR[i * 2 + half];
                    v0 = R * v0 + vbv[2*j]   - M * vgv[2*j];
                    v1 = R * v1 + vbv[2*j+1] - M * vgv[2*j+1];
                }
                if (MODE == 0) {
                    if (!vpart) {
                        int h = cg >> 7, d = cg & 127;
                        int bb2 = r >> 14, l = r & 16383;
                        unsigned u = pack2h(v0, v1);
                        *(unsigned*)(Kb + ((((size_t)(bb2 * 8 + h)) << 14) + l) * 128 + d) = u;
                    } else {
                        st[cl * 136 + rl]       = __float2half_rn(v0);
                        st[(cl + 1) * 136 + rl] = __float2half_rn(v1);
                    }
                } else if (MODE == 1) {
                    int h = cg >> 7, d = cg & 127;
                    int bb2 = r >> 9, q = r & 511;
                    unsigned u = pack2h(QSCALE * v0, QSCALE * v1);
                    *(unsigned*)(Qb + (((size_t)(bb2 * 8 + h)) * 512 + q) * 128 + d) = u;
                } else {
                    *(float2*)(C + (size_t)r * 1024 + cg) = make_float2(v0, v1);
                }
            }
        }
    }
    if (vpart) {
        __syncthreads();
        int bb2 = m0 >> 14, l0 = m0 & 16383;
#pragma unroll
        for (int cl2 = 0; cl2 < 32; cl2++) {
            int c = wid * 32 + cl2;
            int cg = n0 + c - 1024;
            int h = cg >> 7, d = cg & 127;
            uint2 v = *(const uint2*)&st[c * 136 + lane * 4];
            *(uint2*)(Vt + ((size_t)(bb2 * 8 + h) * 128 + d) * LKV + l0 + lane * 4) = v;
        }
    }
}

// ---------------------------------------------------------------------------
// FP16 flash attention (max-free, exp2). Br=128, Bc=64, 256 threads,
// m16n8k16. cp.async 2-stage K/V prefetch.
//   S:  warps 4x2 (q32 x l32);  PV: warps 2x4 (q64 x d32).
// Smem: Q 32KB | stage0 K16+V16 | stage1 K16+V16 | P 16KB (ls overlays P).
// ---------------------------------------------------------------------------
#define AT_Q     0
#define AT_STG   32768
#define AT_P     98304
#define A_SMEM_BYTES 114688

__global__ __launch_bounds__(256, 1)
void attn_h(const __half* __restrict__ Qb, const __half* __restrict__ Kb,
            const __half* __restrict__ Vt, __half* __restrict__ AO)
{
    extern __shared__ char sm[];
    const uint32_t sb = smem_u32(sm);
    const int tid = threadIdx.x;
    const int lane = tid & 31, wid = tid >> 5;
    const int g = lane >> 2, t = lane & 3;
    const int bh = blockIdx.y;
    const int q0 = blockIdx.x * 128;

    const int wq4 = wid & 3, wl = wid >> 2;   // S phase
    const int wq2 = wid & 1, wd = wid >> 1;   // PV phase

    const __half* Qg = Qb + ((size_t)bh * LQ + q0) * DH;
    const __half* Kg = Kb + (size_t)bh * LKV * DH;
    const __half* Vg = Vt + (size_t)bh * DH * LKV;

    const unsigned* Qs = (const unsigned*)(sm + AT_Q);
    unsigned* Ps = (unsigned*)(sm + AT_P);

    // staging assignments
    const __half* k_src[4]; uint32_t k_dst[4];
#pragma unroll
    for (int it = 0; it < 4; it++) {
        int idx = tid + it * 256, row = idx >> 4, blk = idx & 15;
        k_src[it] = Kg + (size_t)row * 128 + blk * 8;
        k_dst[it] = (row * 64 + (((blk ^ row) & 15) << 2)) * 4;
    }
    const __half* v_src[4]; uint32_t v_dst[4];
#pragma unroll
    for (int it = 0; it < 4; it++) {
        int idx = tid + it * 256, d = idx >> 3, blk = idx & 7;
        v_src[it] = Vg + (size_t)d * LKV + blk * 8;
        v_dst[it] = 16384 + (d * 32 + (((blk ^ d) & 7) << 2)) * 4;
    }

    // prologue: Q + chunk0 (group 0), chunk1 (group 1)
#pragma unroll
    for (int it = 0; it < 8; it++) {
        int idx = tid + it * 256, row = idx >> 4, blk = idx & 15;
        cpa16(sb + AT_Q + (row * 64 + (((blk ^ row) & 15) << 2)) * 4,
              Qg + (size_t)row * 128 + blk * 8);
    }
    {   // chunk 0: K off 0, V off 0
        uint32_t base = sb + AT_STG;
#pragma unroll
        for (int it = 0; it < 4; it++) cpa16(base + k_dst[it], k_src[it]);
#pragma unroll
        for (int it = 0; it < 4; it++) cpa16(base + v_dst[it], v_src[it]);
        CP_COMMIT();
    }
    {   // chunk 1: K off 64*128, V off 64
        uint32_t base = sb + AT_STG + 32768;
#pragma unroll
        for (int it = 0; it < 4; it++) cpa16(base + k_dst[it], k_src[it] + (size_t)64 * 128);
#pragma unroll
        for (int it = 0; it < 4; it++) cpa16(base + v_dst[it], v_src[it] + 64);
        CP_COMMIT();
    }

    float oacc[4][4][4];
#pragma unroll
    for (int i = 0; i < 4; i++)
#pragma unroll
        for (int j = 0; j < 4; j++)
#pragma unroll
            for (int r = 0; r < 4; r++) oacc[i][j][r] = 0.f;
    float rsum[2][2] = {{0.f, 0.f}, {0.f, 0.f}};

    const int NC = LKV / 64;
    for (int ci = 0; ci < NC; ci++) {
        CP_WAIT(1);
        __syncthreads();
        const unsigned* Kc = (const unsigned*)(sm + AT_STG + (ci & 1) * 32768);
        const unsigned* Vc = Kc + 4096;

        // ---- S = Q K^T (8 k-steps of 16)
        float sac[2][4][4];
#pragma unroll
        for (int i = 0; i < 2; i++)
#pragma unroll
            for (int j = 0; j < 4; j++)
#pragma unroll
                for (int r = 0; r < 4; r++) sac[i][j][r] = 0.f;
#pragma unroll
        for (int ks = 0; ks < 8; ks++) {
            int kb = ks * 8 + t;
            unsigned afr[2][4], bfr[4][2];
#pragma unroll
            for (int i = 0; i < 2; i++) {
                int m = wq4 * 32 + i * 16 + g;
                afr[i][0] = Qs[swQ64(m,     kb)];
                afr[i][1] = Qs[swQ64(m + 8, kb)];
                afr[i][2] = Qs[swQ64(m,     kb + 4)];
                afr[i][3] = Qs[swQ64(m + 8, kb + 4)];
            }
#pragma unroll
            for (int j = 0; j < 4; j++) {
                int n = wl * 32 + j * 8 + g;
                bfr[j][0] = Kc[swQ64(n, kb)];
                bfr[j][1] = Kc[swQ64(n, kb + 4)];
            }
#pragma unroll
            for (int i = 0; i < 2; i++)
#pragma unroll
                for (int j = 0; j < 4; j++)
                    mma_f16(sac[i][j], afr[i], bfr[j]);
        }

        // ---- P = exp2(S), row sums, store P (half2 words)
#pragma unroll
        for (int i = 0; i < 2; i++) {
            int r0 = wq4 * 32 + i * 16 + g;
#pragma unroll
            for (int j = 0; j < 4; j++) {
                int w = wl * 16 + j * 4 + t;
                float p0 = ex2(sac[i][j][0]);
                float p1 = ex2(sac[i][j][1]);
                float p2 = ex2(sac[i][j][2]);
                float p3 = ex2(sac[i][j][3]);
                rsum[i][0] += p0 + p1;
                rsum[i][1] += p2 + p3;
                Ps[swV32(r0,     w)] = pack2h(p0, p1);
                Ps[swV32(r0 + 8, w)] = pack2h(p2, p3);
            }
        }
        __syncthreads();

        // ---- O += P V (4 k-steps of 16)
#pragma unroll
        for (int ks = 0; ks < 4; ks++) {
            int kb = ks * 8 + t;
            unsigned afr[4][4], bfr[4][2];
#pragma unroll
            for (int i = 0; i < 4; i++) {
                int m = wq2 * 64 + i * 16 + g;
                afr[i][0] = Ps[swV32(m,     kb)];
                afr[i][1] = Ps[swV32(m + 8, kb)];
                afr[i][2] = Ps[swV32(m,     kb + 4)];
                afr[i][3] = Ps[swV32(m + 8, kb + 4)];
            }
#pragma unroll
            for (int j = 0; j < 4; j++) {
                int n = wd * 32 + j * 8 + g;
                bfr[j][0] = Vc[swV32(n, kb)];
                bfr[j][1] = Vc[swV32(n, kb + 4)];
            }
#pragma unroll
            for (int i = 0; i < 4; i++)
#pragma unroll
                for (int j = 0; j < 4; j++)
                    mma_f16(oacc[i][j], afr[i], bfr[j]);
        }
        __syncthreads();

        if (ci + 2 < NC) {
            uint32_t base = sb + AT_STG + (ci & 1) * 32768;
            size_t koff = (size_t)(ci + 2) * 64 * 128;
            int voff = (ci + 2) * 64;
#pragma unroll
            for (int it = 0; it < 4; it++) cpa16(base + k_dst[it], k_src[it] + koff);
#pragma unroll
            for (int it = 0; it < 4; it++) cpa16(base + v_dst[it], v_src[it] + voff);
        }
        CP_COMMIT();
    }

    // ---- row-sum reduction (ls overlays P region)
    float* ls = (float*)Ps;
#pragma unroll
    for (int i = 0; i < 2; i++)
#pragma unroll
        for (int h = 0; h < 2; h++) {
            float v = rsum[i][h];
            v += __shfl_xor_sync(0xffffffffu, v, 1);
            v += __shfl_xor_sync(0xffffffffu, v, 2);
            rsum[i][h] = v;
        }
    if (t == 0) {
#pragma unroll
        for (int i = 0; i < 2; i++) {
            int r = wq4 * 32 + i * 16 + g;
            ls[wl * 128 + r]     = rsum[i][0];
            ls[wl * 128 + r + 8] = rsum[i][1];
        }
    }
    __syncthreads();

    // ---- epilogue: normalize, scatter (half2)
    int bb2 = bh >> 3, h = bh & 7;
#pragma unroll
    for (int i = 0; i < 4; i++) {
#pragma unroll
        for (int half = 0; half < 2; half++) {
            int r = wq2 * 64 + i * 16 + g + half * 8;
            float inv = 1.f / (ls[r] + ls[128 + r]);
            size_t rowoff = ((size_t)(bb2 * 512 + q0 + r)) * 1024 + h * 128;
#pragma unroll
            for (int j = 0; j < 4; j++) {
                int cc = wd * 32 + j * 8 + 2 * t;
                *(unsigned*)(AO + rowoff + cc) =
                    pack2h(oacc[i][j][half * 2] * inv, oacc[i][j][half * 2 + 1] * inv);
            }
        }
    }
}

// ---------------------------------------------------------------------------
// Launcher. Launch order puts gemm_h<0> (KV, the hot kernel) at index 5 so
// the profiler's "-s 5 -c 1" captures it.
// ---------------------------------------------------------------------------
extern "C" void kernel_launch(void* const* d_in, const int* in_sizes, int n_in,
                              void* d_out, int out_size)
{
    (void)in_sizes; (void)n_in; (void)out_size;
    const float* latent   = (const float*)d_in[0];
    const float* inpkv    = (const float*)d_in[1];
    const float* W_Q      = (const float*)d_in[2];
    const float* W_K      = (const float*)d_in[3];
    const float* W_V      = (const float*)d_in[4];
    const float* W_O      = (const float*)d_in[5];
    const float* ln_lat_g = (const float*)d_in[6];
    const float* ln_lat_b = (const float*)d_in[7];
    const float* ln_in_g  = (const float*)d_in[8];
    const float* ln_in_b  = (const float*)d_in[9];
    float* out = (float*)d_out;

    float *p_mukv, *p_rskv, *p_muq, *p_rsq, *p_vb, *p_vg, *p_vbq, *p_vgq;
    void *p_Xkv, *p_Xq, *p_Q, *p_K, *p_Vt, *p_AO, *p_WTkv, *p_WTq, *p_WTo;
    cudaGetSymbolAddress((void**)&p_mukv, g_mu_kv);
    cudaGetSymbolAddress((void**)&p_rskv, g_rs_kv);
    cudaGetSymbolAddress((void**)&p_muq,  g_mu_q);
    cudaGetSymbolAddress((void**)&p_rsq,  g_rs_q);
    cudaGetSymbolAddress(&p_Xkv,  g_Xkv4);
    cudaGetSymbolAddress(&p_Xq,   g_Xq4);
    cudaGetSymbolAddress(&p_Q,    g_Qb4);
    cudaGetSymbolAddress(&p_K,    g_Kb4);
    cudaGetSymbolAddress(&p_Vt,   g_Vt4);
    cudaGetSymbolAddress(&p_AO,   g_AO4);
    cudaGetSymbolAddress(&p_WTkv, g_WTkv4);
    cudaGetSymbolAddress(&p_WTq,  g_WTq4);
    cudaGetSymbolAddress(&p_WTo,  g_WTo4);
    cudaGetSymbolAddress((void**)&p_vb,  g_vb);
    cudaGetSymbolAddress((void**)&p_vg,  g_vg);
    cudaGetSymbolAddress((void**)&p_vbq, g_vbq);
    cudaGetSymbolAddress((void**)&p_vgq, g_vgq);

    cudaFuncSetAttribute(gemm_h<0>, cudaFuncAttributeMaxDynamicSharedMemorySize, G_SMEM);
    cudaFuncSetAttribute(gemm_h<1>, cudaFuncAttributeMaxDynamicSharedMemorySize, G_SMEM);
    cudaFuncSetAttribute(gemm_h<2>, cudaFuncAttributeMaxDynamicSharedMemorySize, G_SMEM);
    cudaFuncSetAttribute(attn_h,    cudaFuncAttributeMaxDynamicSharedMemorySize, A_SMEM_BYTES);

    dim3 tb(32, 8);
    // 0,1: LN row stats + half copies
    rowstats_kernel<<<MKV / 8, 256>>>(inpkv,  (__half*)p_Xkv, p_mukv, p_rskv, CH_IN);
    rowstats_kernel<<<MQ  / 8, 256>>>(latent, (__half*)p_Xq,  p_muq,  p_rsq,  CH_LAT);
    // 2,3: K|V weight transposes (gamma folded)
    wtrans_kernel<<<dim3(32, 24), tb>>>(W_K, (__half*)p_WTkv,              768, 1024, ln_in_g);
    wtrans_kernel<<<dim3(32, 24), tb>>>(W_V, (__half*)p_WTkv + 1024 * 768, 768, 1024, ln_in_g);
    // 4: LN fold vectors for K|V (one launch)
    vbvg_kernel<<<8, 256>>>(W_K, W_V, ln_in_g, ln_in_b, p_vb, p_vg, 768);
    // 5: K|V projection  <-- profiled launch
    gemm_h<0><<<dim3(8, 1024), 256, G_SMEM>>>((const __half*)p_Xkv, (const __half*)p_WTkv,
                                              p_mukv, p_rskv, p_vb, p_vg, nullptr, CH_IN);
    // 6,7: Q weight prep
    wtrans_kernel<<<dim3(32, 32), tb>>>(W_Q, (__half*)p_WTq, 1024, 1024, ln_lat_g);
    vbvg_kernel<<<4, 256>>>(W_Q, W_Q, ln_lat_g, ln_lat_b, p_vbq, p_vgq, 1024);
    // 8: Q projection
    gemm_h<1><<<dim3(4, 32), 256, G_SMEM>>>((const __half*)p_Xq, (const __half*)p_WTq,
                                            p_muq, p_rsq, p_vbq, p_vgq, nullptr, CH_LAT);
    // 9: flash attention
    attn_h<<<dim3(4, BH), 256, A_SMEM_BYTES>>>((const __half*)p_Q, (const __half*)p_K,
                                               (const __half*)p_Vt, (__half*)p_AO);
    // 10: O weight transpose
    wtrans_kernel<<<dim3(32, 32), tb>>>(W_O, (__half*)p_WTo, 1024, 1024, nullptr);
    // 11: output projection (float out)
    gemm_h<2><<<dim3(4, 32), 256, G_SMEM>>>((const __half*)p_AO, (const __half*)p_WTo,
                                            nullptr, nullptr, nullptr, nullptr, out, 1024);
}